// round 2
// baseline (speedup 1.0000x reference)
#include <cuda_runtime.h>
#include <math.h>

#define S_LEN 4680
#define DIM 1536
#define NH 12
#define HD 128

// ---------------- static scratch (no allocs allowed) ----------------
__device__ float g_Q [S_LEN*DIM];
__device__ float g_K [S_LEN*DIM];
__device__ float g_V [S_LEN*DIM];
__device__ float g_RQ[S_LEN*DIM];
__device__ float g_RK[S_LEN*DIM];
__device__ float g_XL[S_LEN*DIM];
__device__ float g_Z [S_LEN*NH];
__device__ float g_G2[NH*HD*HD];
__device__ float g_WT[HD*HD];

// ---------------- GEMM: C[M,N] = A[M,K] @ W[N,K]^T + bias ----------------
// Tiles: 128x64x16, 256 threads, 8x4 per thread.
__global__ void gemm_bias_kernel(const float* __restrict__ A,
                                 const float* __restrict__ W,
                                 const float* __restrict__ bias,
                                 float* __restrict__ C,
                                 int M, int N, int K) {
    __shared__ float As[16][128];
    __shared__ float Bs[16][64];
    const int tid = threadIdx.x;
    const int block_m = blockIdx.y * 128;
    const int block_n = blockIdx.x * 64;
    const int ty = tid >> 4;   // 0..15 -> rows ty*8..ty*8+7
    const int tx = tid & 15;   // 0..15 -> cols tx*4..tx*4+3

    float acc[8][4];
#pragma unroll
    for (int i = 0; i < 8; i++)
#pragma unroll
        for (int j = 0; j < 4; j++) acc[i][j] = 0.f;

    const int lr = tid >> 2;        // 0..63
    const int lk = (tid & 3) * 4;   // 0,4,8,12

    for (int k0 = 0; k0 < K; k0 += 16) {
        // load A tile (128x16) as float4, transposed into As[k][m]
#pragma unroll
        for (int rpt = 0; rpt < 2; rpt++) {
            int m = lr + rpt * 64;
            int gm = block_m + m;
            float4 v = make_float4(0.f, 0.f, 0.f, 0.f);
            if (gm < M) v = *(const float4*)(A + (size_t)gm * K + k0 + lk);
            As[lk + 0][m] = v.x; As[lk + 1][m] = v.y;
            As[lk + 2][m] = v.z; As[lk + 3][m] = v.w;
        }
        // load W tile (64x16) into Bs[k][n]
        {
            int n = lr;
            float4 v = *(const float4*)(W + (size_t)(block_n + n) * K + k0 + lk);
            Bs[lk + 0][n] = v.x; Bs[lk + 1][n] = v.y;
            Bs[lk + 2][n] = v.z; Bs[lk + 3][n] = v.w;
        }
        __syncthreads();
#pragma unroll
        for (int kk = 0; kk < 16; kk++) {
            float a[8], b[4];
            float4 a0 = *(const float4*)&As[kk][ty * 8];
            float4 a1 = *(const float4*)&As[kk][ty * 8 + 4];
            a[0]=a0.x; a[1]=a0.y; a[2]=a0.z; a[3]=a0.w;
            a[4]=a1.x; a[5]=a1.y; a[6]=a1.z; a[7]=a1.w;
            float4 b0 = *(const float4*)&Bs[kk][tx * 4];
            b[0]=b0.x; b[1]=b0.y; b[2]=b0.z; b[3]=b0.w;
#pragma unroll
            for (int i = 0; i < 8; i++)
#pragma unroll
                for (int j = 0; j < 4; j++) acc[i][j] += a[i] * b[j];
        }
        __syncthreads();
    }
    const float4 b4 = *(const float4*)(bias + block_n + tx * 4);
#pragma unroll
    for (int i = 0; i < 8; i++) {
        int gm = block_m + ty * 8 + i;
        if (gm < M) {
            float4 o = make_float4(acc[i][0] + b4.x, acc[i][1] + b4.y,
                                   acc[i][2] + b4.z, acc[i][3] + b4.w);
            *(float4*)(C + (size_t)gm * N + block_n + tx * 4) = o;
        }
    }
}

// ---------------- RMSNorm (in place, row = 1536) ----------------
__global__ void rmsnorm_kernel(float* __restrict__ X, const float* __restrict__ gw) {
    int row = blockIdx.x;
    float* x = X + (size_t)row * DIM;
    float ss = 0.f;
    for (int i = threadIdx.x; i < DIM; i += 256) { float v = x[i]; ss += v * v; }
    __shared__ float red[8];
    __shared__ float s_scale;
    int lane = threadIdx.x & 31, wid = threadIdx.x >> 5;
#pragma unroll
    for (int o = 16; o > 0; o >>= 1) ss += __shfl_xor_sync(0xffffffffu, ss, o);
    if (lane == 0) red[wid] = ss;
    __syncthreads();
    if (wid == 0) {
        float v = (lane < 8) ? red[lane] : 0.f;
#pragma unroll
        for (int o = 4; o > 0; o >>= 1) v += __shfl_xor_sync(0xffffffffu, v, o);
        if (lane == 0) s_scale = rsqrtf(v / (float)DIM + 1e-6f);
    }
    __syncthreads();
    float sc = s_scale;
    for (int i = threadIdx.x; i < DIM; i += 256) x[i] = x[i] * sc * gw[i];
}

// ---------------- z = 1/(relu(q)·g_kmean + 1e-6), one warp per (s,n) ----------------
__global__ void z_kernel(const float* __restrict__ Q, const float* __restrict__ gkm,
                         float* __restrict__ Z) {
    int idx = (blockIdx.x * blockDim.x + threadIdx.x) >> 5;
    if (idx >= S_LEN * NH) return;
    int lane = threadIdx.x & 31;
    int n = idx % NH;
    const float* q = Q + (size_t)idx * HD;
    float sum = 0.f;
#pragma unroll
    for (int d = lane; d < HD; d += 32) sum += fmaxf(q[d], 0.f) * gkm[n * HD + d];
#pragma unroll
    for (int o = 16; o > 0; o >>= 1) sum += __shfl_xor_sync(0xffffffffu, sum, o);
    if (lane == 0) Z[idx] = 1.f / (sum + 1e-6f);
}

// ---------------- 3D RoPE: one thread per (s, n, pair) ----------------
__global__ void rope_kernel(const float* __restrict__ X, float* __restrict__ Y,
                            const float* __restrict__ freqs) {
    int gid = blockIdx.x * blockDim.x + threadIdx.x;
    const int total = S_LEN * NH * 64;
    if (gid >= total) return;
    int i = gid & 63;
    int sn = gid >> 6;
    int s = sn / NH;
    int w = s % 52;
    int h = (s / 52) % 30;
    int f = s / (52 * 30);
    int pos;
    if (i < 22) pos = f; else if (i < 43) pos = h; else pos = w;
    float cr = freqs[(pos * 64 + i) * 2 + 0];
    float ci = freqs[(pos * 64 + i) * 2 + 1];
    size_t base = (size_t)sn * HD + 2 * i;
    float xr = X[base], xi = X[base + 1];
    Y[base]     = xr * cr - xi * ci;
    Y[base + 1] = xr * ci + xi * cr;
}

// ---------------- Wlin transpose (128x128) ----------------
__global__ void transpose128_kernel(const float* __restrict__ in, float* __restrict__ out) {
    int j = blockIdx.x, m = threadIdx.x;
    out[m * HD + j] = in[j * HD + m];
}

// ---------------- G2[n,d,j] = sum_m g_kv[n,d,m] * Wlin[j,m] ----------------
__global__ void g2_kernel(const float* __restrict__ gkv, const float* __restrict__ WT,
                          float* __restrict__ G2) {
    int nd = blockIdx.x;   // n*128 + d
    __shared__ float kv[HD];
    kv[threadIdx.x] = gkv[(size_t)nd * HD + threadIdx.x];
    __syncthreads();
    int j = threadIdx.x;
    float sum = 0.f;
#pragma unroll 8
    for (int m = 0; m < HD; m++) sum += kv[m] * WT[m * HD + j];
    G2[(size_t)nd * HD + j] = sum;
}

// ---------------- XL[s,n,:] += z * (rq @ G2[n]) + blin ----------------
__global__ void xg_kernel(const float* __restrict__ RQ, const float* __restrict__ G2,
                          const float* __restrict__ Z, const float* __restrict__ blin,
                          float* __restrict__ XL) {
    int sn = blockIdx.x;
    int n = sn % NH;
    int j = threadIdx.x;
    __shared__ float rq[HD];
    rq[j] = RQ[(size_t)sn * HD + j];
    __syncthreads();
    const float* g2 = G2 + (size_t)n * HD * HD;
    float sum = 0.f;
#pragma unroll 8
    for (int d = 0; d < HD; d++) sum += rq[d] * g2[d * HD + j];
    XL[(size_t)sn * HD + j] += sum * Z[sn] + blin[j];
}

// ---------------- flash attention, fp32, Br=Bc=64 ----------------
// dynamic smem: Qs[64][132] Ks[64][132] Vs[64][132] Sc[64][68]
#define ATT_SMEM_FLOATS (3 * 64 * 132 + 64 * 68)
__global__ void attn_kernel(const float* __restrict__ RQ, const float* __restrict__ RK,
                            const float* __restrict__ V, float* __restrict__ XL) {
    extern __shared__ float sm[];
    float* Qs = sm;
    float* Ks = sm + 64 * 132;
    float* Vs = sm + 2 * 64 * 132;
    float* Sc = sm + 3 * 64 * 132;
    const int tid  = threadIdx.x;
    const int head = blockIdx.y;
    const int q0   = blockIdx.x * 64;
    // load Q tile
#pragma unroll
    for (int it = 0; it < 8; it++) {
        int idx = it * 256 + tid;
        int row = idx >> 5;
        int c4  = (idx & 31) * 4;
        int s = q0 + row;
        float4 v = make_float4(0.f, 0.f, 0.f, 0.f);
        if (s < S_LEN) v = *(const float4*)(RQ + ((size_t)s * NH + head) * HD + c4);
        *(float4*)&Qs[row * 132 + c4] = v;
    }
    const int r  = tid >> 2;   // row 0..63
    const int g  = tid & 3;    // col group (32 cols each / 16 scores each)
    const int ty = tid >> 4;
    const int tx = tid & 15;
    float acc[32];
#pragma unroll
    for (int c = 0; c < 32; c++) acc[c] = 0.f;
    float m_run = -1e30f, l_run = 0.f;
    const float scale = 0.08838834764831845f;  // 128^-0.5

    for (int k0 = 0; k0 < S_LEN; k0 += 64) {
        __syncthreads();
        // load K, V tiles
#pragma unroll
        for (int it = 0; it < 8; it++) {
            int idx = it * 256 + tid;
            int row = idx >> 5;
            int c4  = (idx & 31) * 4;
            int s = k0 + row;
            float4 kv = make_float4(0.f, 0.f, 0.f, 0.f);
            float4 vv = make_float4(0.f, 0.f, 0.f, 0.f);
            if (s < S_LEN) {
                size_t off = ((size_t)s * NH + head) * HD + c4;
                kv = *(const float4*)(RK + off);
                vv = *(const float4*)(V + off);
            }
            *(float4*)&Ks[row * 132 + c4] = kv;
            *(float4*)&Vs[row * 132 + c4] = vv;
        }
        __syncthreads();
        // scores 64x64: 16x16 threads, 4x4 each, vectorized over d
        float sc[4][4];
#pragma unroll
        for (int i = 0; i < 4; i++)
#pragma unroll
            for (int j = 0; j < 4; j++) sc[i][j] = 0.f;
#pragma unroll 4
        for (int d = 0; d < HD; d += 4) {
            float4 a[4], b[4];
#pragma unroll
            for (int i = 0; i < 4; i++) a[i] = *(const float4*)&Qs[(ty * 4 + i) * 132 + d];
#pragma unroll
            for (int j = 0; j < 4; j++) b[j] = *(const float4*)&Ks[(tx * 4 + j) * 132 + d];
#pragma unroll
            for (int i = 0; i < 4; i++)
#pragma unroll
                for (int j = 0; j < 4; j++)
                    sc[i][j] += a[i].x * b[j].x + a[i].y * b[j].y
                              + a[i].z * b[j].z + a[i].w * b[j].w;
        }
#pragma unroll
        for (int i = 0; i < 4; i++)
#pragma unroll
            for (int j = 0; j < 4; j++) {
                float v = sc[i][j] * scale;
                if (k0 + tx * 4 + j >= S_LEN) v = -1e30f;
                Sc[(ty * 4 + i) * 68 + tx * 4 + j] = v;
            }
        __syncthreads();
        // online softmax: 4 threads per row
        float mloc = -1e30f;
#pragma unroll
        for (int j = 0; j < 16; j++) mloc = fmaxf(mloc, Sc[r * 68 + g * 16 + j]);
        mloc = fmaxf(mloc, __shfl_xor_sync(0xffffffffu, mloc, 1));
        mloc = fmaxf(mloc, __shfl_xor_sync(0xffffffffu, mloc, 2));
        float mnew = fmaxf(m_run, mloc);
        float corr = __expf(m_run - mnew);
        float psum = 0.f;
#pragma unroll
        for (int j = 0; j < 16; j++) {
            float p = __expf(Sc[r * 68 + g * 16 + j] - mnew);
            Sc[r * 68 + g * 16 + j] = p;
            psum += p;
        }
        psum += __shfl_xor_sync(0xffffffffu, psum, 1);
        psum += __shfl_xor_sync(0xffffffffu, psum, 2);
        l_run = l_run * corr + psum;
        m_run = mnew;
#pragma unroll
        for (int c = 0; c < 32; c++) acc[c] *= corr;
        __syncthreads();
        // P @ V
#pragma unroll 4
        for (int j = 0; j < 64; j++) {
            float p = Sc[r * 68 + j];
            const float* vr = &Vs[j * 132 + g * 32];
#pragma unroll
            for (int c = 0; c < 32; c += 4) {
                float4 v4 = *(const float4*)&vr[c];
                acc[c]     += p * v4.x;
                acc[c + 1] += p * v4.y;
                acc[c + 2] += p * v4.z;
                acc[c + 3] += p * v4.w;
            }
        }
    }
    float inv_l = 1.f / l_run;
    int s = q0 + r;
    if (s < S_LEN) {
        float* outp = XL + ((size_t)s * NH + head) * HD + g * 32;
#pragma unroll
        for (int c = 0; c < 32; c += 4) {
            float4 o = make_float4(acc[c] * inv_l, acc[c + 1] * inv_l,
                                   acc[c + 2] * inv_l, acc[c + 3] * inv_l);
            *(float4*)&outp[c] = o;
        }
    }
}

// ---------------- launch ----------------
extern "C" void kernel_launch(void* const* d_in, const int* in_sizes, int n_in,
                              void* d_out, int out_size) {
    const float* x    = (const float*)d_in[0];
    const float* freqs= (const float*)d_in[1];
    const float* gkm  = (const float*)d_in[2];
    const float* gkv  = (const float*)d_in[3];
    const float* Wq   = (const float*)d_in[4];
    const float* bq   = (const float*)d_in[5];
    const float* Wk   = (const float*)d_in[6];
    const float* bk   = (const float*)d_in[7];
    const float* Wv   = (const float*)d_in[8];
    const float* bv   = (const float*)d_in[9];
    const float* Wo   = (const float*)d_in[10];
    const float* bo   = (const float*)d_in[11];
    const float* gq   = (const float*)d_in[12];
    const float* gk   = (const float*)d_in[13];
    const float* Wlin = (const float*)d_in[14];
    const float* blin = (const float*)d_in[15];
    float* out = (float*)d_out;

    float *Qp, *Kp, *Vp, *RQp, *RKp, *XLp, *Zp, *G2p, *WTp;
    cudaGetSymbolAddress((void**)&Qp,  g_Q);
    cudaGetSymbolAddress((void**)&Kp,  g_K);
    cudaGetSymbolAddress((void**)&Vp,  g_V);
    cudaGetSymbolAddress((void**)&RQp, g_RQ);
    cudaGetSymbolAddress((void**)&RKp, g_RK);
    cudaGetSymbolAddress((void**)&XLp, g_XL);
    cudaGetSymbolAddress((void**)&Zp,  g_Z);
    cudaGetSymbolAddress((void**)&G2p, g_G2);
    cudaGetSymbolAddress((void**)&WTp, g_WT);

    const int smem_attn = ATT_SMEM_FLOATS * sizeof(float);
    cudaFuncSetAttribute(attn_kernel, cudaFuncAttributeMaxDynamicSharedMemorySize, smem_attn);

    dim3 gemm_grid(DIM / 64, (S_LEN + 127) / 128);
    // Q, K, V projections
    gemm_bias_kernel<<<gemm_grid, 256>>>(x, Wq, bq, Qp, S_LEN, DIM, DIM);
    gemm_bias_kernel<<<gemm_grid, 256>>>(x, Wk, bk, Kp, S_LEN, DIM, DIM);
    gemm_bias_kernel<<<gemm_grid, 256>>>(x, Wv, bv, Vp, S_LEN, DIM, DIM);
    // RMSNorm q, k
    rmsnorm_kernel<<<S_LEN, 256>>>(Qp, gq);
    rmsnorm_kernel<<<S_LEN, 256>>>(Kp, gk);
    // z from post-RMS q (pre-RoPE)
    {
        int warps = S_LEN * NH;
        int threads = 256;
        int blocks = (warps * 32 + threads - 1) / threads;
        z_kernel<<<blocks, threads>>>(Qp, gkm, Zp);
    }
    // RoPE
    {
        int total = S_LEN * NH * 64;
        rope_kernel<<<(total + 255) / 256, 256>>>(Qp, RQp, freqs);
        rope_kernel<<<(total + 255) / 256, 256>>>(Kp, RKp, freqs);
    }
    // G2 = g_kv @ Wlin^T (folded small GEMM)
    transpose128_kernel<<<HD, HD>>>(Wlin, WTp);
    g2_kernel<<<NH * HD, HD>>>(gkv, WTp, G2p);
    // attention -> XL
    {
        dim3 grid((S_LEN + 63) / 64, NH);
        attn_kernel<<<grid, 256, smem_attn>>>(RQp, RKp, Vp, XLp);
    }
    // XL += z * (rq @ G2) + blin
    xg_kernel<<<S_LEN * NH, HD>>>(RQp, G2p, Zp, blin, XLp);
    // out = XL @ Wo^T + bo
    gemm_bias_kernel<<<gemm_grid, 256>>>(XLp, Wo, bo, out, S_LEN, DIM, DIM);
}

// round 3
// speedup vs baseline: 9.1764x; 9.1764x over previous
#include <cuda_runtime.h>
#include <math.h>
#include <stdint.h>

#define S_LEN 4680
#define DIM 1536
#define NH 12
#define HD 128

// ---------------- static scratch ----------------
__device__ float g_Q [S_LEN*DIM];
__device__ float g_K [S_LEN*DIM];
__device__ float g_V [S_LEN*DIM];
__device__ float g_RQ[S_LEN*DIM];
__device__ float g_RK[S_LEN*DIM];
__device__ float g_XL[S_LEN*DIM];
__device__ float g_Z [S_LEN*NH];
__device__ float g_G2[NH*HD*HD];
__device__ float g_WT[HD*HD];

// ---------------- helpers ----------------
__device__ __forceinline__ uint32_t f2tf32(float f) {
    uint32_t u;
    asm("cvt.rna.tf32.f32 %0, %1;" : "=r"(u) : "f"(f));
    return u;
}
__device__ __forceinline__ void mma_tf32(float c[4],
                                         uint32_t a0, uint32_t a1, uint32_t a2, uint32_t a3,
                                         uint32_t b0, uint32_t b1) {
    asm("mma.sync.aligned.m16n8k8.row.col.f32.tf32.tf32.f32 "
        "{%0,%1,%2,%3},{%4,%5,%6,%7},{%8,%9},{%0,%1,%2,%3};"
        : "+f"(c[0]), "+f"(c[1]), "+f"(c[2]), "+f"(c[3])
        : "r"(a0), "r"(a1), "r"(a2), "r"(a3), "r"(b0), "r"(b1));
}

// ---------------- TF32 GEMM: C[M,N] = A[M,K] @ W[N,K]^T + bias ----------------
// 128x128x32 tiles, 256 thr / 8 warps (2m x 4n), warp tile 64x32.
#define GPAD 36
__global__ __launch_bounds__(256) void gemm_tc_kernel(
    const float* __restrict__ A, const float* __restrict__ W,
    const float* __restrict__ bias, float* __restrict__ C,
    int M, int N, int K) {
    __shared__ float As[128 * GPAD];
    __shared__ float Bs[128 * GPAD];
    const int tid = threadIdx.x;
    const int warp = tid >> 5, lane = tid & 31;
    const int g = lane >> 2, t = lane & 3;
    const int wm = warp >> 2, wn = warp & 3;   // 2 x 4
    const int bm = blockIdx.y * 128, bn = blockIdx.x * 128;

    float acc[4][4][4];
#pragma unroll
    for (int i = 0; i < 4; i++)
#pragma unroll
        for (int j = 0; j < 4; j++)
#pragma unroll
            for (int r = 0; r < 4; r++) acc[i][j][r] = 0.f;

    for (int k0 = 0; k0 < K; k0 += 32) {
        // A tile 128x32 (guard M), W tile 128x32
#pragma unroll
        for (int it = 0; it < 4; it++) {
            int f4 = it * 256 + tid;          // 0..1023
            int row = f4 >> 3, c4 = (f4 & 7) * 4;
            float4 v = make_float4(0.f, 0.f, 0.f, 0.f);
            int gm = bm + row;
            if (gm < M) v = *(const float4*)(A + (size_t)gm * K + k0 + c4);
            float* d = As + row * GPAD + c4;
            d[0] = __uint_as_float(f2tf32(v.x));
            d[1] = __uint_as_float(f2tf32(v.y));
            d[2] = __uint_as_float(f2tf32(v.z));
            d[3] = __uint_as_float(f2tf32(v.w));
            float4 w = *(const float4*)(W + (size_t)(bn + row) * K + k0 + c4);
            float* e = Bs + row * GPAD + c4;
            e[0] = __uint_as_float(f2tf32(w.x));
            e[1] = __uint_as_float(f2tf32(w.y));
            e[2] = __uint_as_float(f2tf32(w.z));
            e[3] = __uint_as_float(f2tf32(w.w));
        }
        __syncthreads();
#pragma unroll
        for (int ks = 0; ks < 4; ks++) {
            int kk = ks * 8;
            uint32_t af[4][4], bf[4][2];
#pragma unroll
            for (int mt = 0; mt < 4; mt++) {
                const float* p = As + (wm * 64 + mt * 16) * GPAD + kk;
                af[mt][0] = __float_as_uint(p[(g    ) * GPAD + t    ]);
                af[mt][1] = __float_as_uint(p[(g + 8) * GPAD + t    ]);
                af[mt][2] = __float_as_uint(p[(g    ) * GPAD + t + 4]);
                af[mt][3] = __float_as_uint(p[(g + 8) * GPAD + t + 4]);
            }
#pragma unroll
            for (int nt = 0; nt < 4; nt++) {
                const float* p = Bs + (wn * 32 + nt * 8 + g) * GPAD + kk;
                bf[nt][0] = __float_as_uint(p[t]);
                bf[nt][1] = __float_as_uint(p[t + 4]);
            }
#pragma unroll
            for (int mt = 0; mt < 4; mt++)
#pragma unroll
                for (int nt = 0; nt < 4; nt++)
                    mma_tf32(acc[mt][nt], af[mt][0], af[mt][1], af[mt][2], af[mt][3],
                             bf[nt][0], bf[nt][1]);
        }
        __syncthreads();
    }
    // epilogue
#pragma unroll
    for (int mt = 0; mt < 4; mt++) {
#pragma unroll
        for (int nt = 0; nt < 4; nt++) {
            int col = bn + wn * 32 + nt * 8 + 2 * t;
            float2 b2 = *(const float2*)(bias + col);
            int r0 = bm + wm * 64 + mt * 16 + g;
            int r1 = r0 + 8;
            if (r0 < M) {
                float2 o = make_float2(acc[mt][nt][0] + b2.x, acc[mt][nt][1] + b2.y);
                *(float2*)(C + (size_t)r0 * N + col) = o;
            }
            if (r1 < M) {
                float2 o = make_float2(acc[mt][nt][2] + b2.x, acc[mt][nt][3] + b2.y);
                *(float2*)(C + (size_t)r1 * N + col) = o;
            }
        }
    }
}

// ---------------- RMSNorm ----------------
__global__ void rmsnorm_kernel(float* __restrict__ X, const float* __restrict__ gw) {
    int row = blockIdx.x;
    float* x = X + (size_t)row * DIM;
    float ss = 0.f;
    for (int i = threadIdx.x; i < DIM; i += 256) { float v = x[i]; ss += v * v; }
    __shared__ float red[8];
    __shared__ float s_scale;
    int lane = threadIdx.x & 31, wid = threadIdx.x >> 5;
#pragma unroll
    for (int o = 16; o > 0; o >>= 1) ss += __shfl_xor_sync(0xffffffffu, ss, o);
    if (lane == 0) red[wid] = ss;
    __syncthreads();
    if (wid == 0) {
        float v = (lane < 8) ? red[lane] : 0.f;
#pragma unroll
        for (int o = 4; o > 0; o >>= 1) v += __shfl_xor_sync(0xffffffffu, v, o);
        if (lane == 0) s_scale = rsqrtf(v / (float)DIM + 1e-6f);
    }
    __syncthreads();
    float sc = s_scale;
    for (int i = threadIdx.x; i < DIM; i += 256) x[i] = x[i] * sc * gw[i];
}

// ---------------- z ----------------
__global__ void z_kernel(const float* __restrict__ Q, const float* __restrict__ gkm,
                         float* __restrict__ Z) {
    int idx = (blockIdx.x * blockDim.x + threadIdx.x) >> 5;
    if (idx >= S_LEN * NH) return;
    int lane = threadIdx.x & 31;
    int n = idx % NH;
    const float* q = Q + (size_t)idx * HD;
    float sum = 0.f;
#pragma unroll
    for (int d = lane; d < HD; d += 32) sum += fmaxf(q[d], 0.f) * gkm[n * HD + d];
#pragma unroll
    for (int o = 16; o > 0; o >>= 1) sum += __shfl_xor_sync(0xffffffffu, sum, o);
    if (lane == 0) Z[idx] = 1.f / (sum + 1e-6f);
}

// ---------------- RoPE ----------------
__global__ void rope_kernel(const float* __restrict__ X, float* __restrict__ Y,
                            const float* __restrict__ freqs) {
    int gid = blockIdx.x * blockDim.x + threadIdx.x;
    const int total = S_LEN * NH * 64;
    if (gid >= total) return;
    int i = gid & 63;
    int sn = gid >> 6;
    int s = sn / NH;
    int w = s % 52;
    int h = (s / 52) % 30;
    int f = s / (52 * 30);
    int pos;
    if (i < 22) pos = f; else if (i < 43) pos = h; else pos = w;
    float cr = freqs[(pos * 64 + i) * 2 + 0];
    float ci = freqs[(pos * 64 + i) * 2 + 1];
    size_t base = (size_t)sn * HD + 2 * i;
    float xr = X[base], xi = X[base + 1];
    Y[base]     = xr * cr - xi * ci;
    Y[base + 1] = xr * ci + xi * cr;
}

// ---------------- Wlin transpose ----------------
__global__ void transpose128_kernel(const float* __restrict__ in, float* __restrict__ out) {
    int j = blockIdx.x, m = threadIdx.x;
    out[m * HD + j] = in[j * HD + m];
}

// ---------------- G2 = g_kv @ Wlin^T ----------------
__global__ void g2_kernel(const float* __restrict__ gkv, const float* __restrict__ WT,
                          float* __restrict__ G2) {
    int nd = blockIdx.x;
    __shared__ float kv[HD];
    kv[threadIdx.x] = gkv[(size_t)nd * HD + threadIdx.x];
    __syncthreads();
    int j = threadIdx.x;
    float sum = 0.f;
#pragma unroll 8
    for (int m = 0; m < HD; m++) sum += kv[m] * WT[m * HD + j];
    G2[(size_t)nd * HD + j] = sum;
}

// ---------------- XL += z*(rq@G2) + blin ----------------
__global__ void xg_kernel(const float* __restrict__ RQ, const float* __restrict__ G2,
                          const float* __restrict__ Z, const float* __restrict__ blin,
                          float* __restrict__ XL) {
    int sn = blockIdx.x;
    int n = sn % NH;
    int j = threadIdx.x;
    __shared__ float rq[HD];
    rq[j] = RQ[(size_t)sn * HD + j];
    __syncthreads();
    const float* g2 = G2 + (size_t)n * HD * HD;
    float sum = 0.f;
#pragma unroll 8
    for (int d = 0; d < HD; d++) sum += rq[d] * g2[d * HD + j];
    XL[(size_t)sn * HD + j] += sum * Z[sn] + blin[j];
}

// ---------------- TF32 flash attention ----------------
// Br=128 (8 warps x m16), Bc=64, HD=128.
// smem: Ks[64*132] Vs[64*132] Ps[128*68]; Q staged into Ks+Vs region.
#define KPAD 132
#define PPAD 68
#define ATT_SMEM ((2 * 64 * KPAD + 128 * PPAD) * 4)
__global__ __launch_bounds__(256, 1) void attn_tc_kernel(
    const float* __restrict__ RQ, const float* __restrict__ RK,
    const float* __restrict__ V, float* __restrict__ XL) {
    extern __shared__ float sm[];
    float* Ks = sm;
    float* Vs = sm + 64 * KPAD;
    float* Ps = sm + 2 * 64 * KPAD;
    float* Qstage = sm;   // 128*132 == 2*64*132, aliases Ks+Vs

    const int tid = threadIdx.x;
    const int warp = tid >> 5, lane = tid & 31;
    const int g = lane >> 2, t = lane & 3;
    const int head = blockIdx.y;
    const int q0 = blockIdx.x * 128;

    // ---- stage Q tile (128x128) and load register fragments ----
#pragma unroll
    for (int it = 0; it < 16; it++) {
        int f4 = it * 256 + tid;            // 0..4095
        int row = f4 >> 5, c4 = (f4 & 31) * 4;
        int s = q0 + row;
        float4 v = make_float4(0.f, 0.f, 0.f, 0.f);
        if (s < S_LEN) v = *(const float4*)(RQ + ((size_t)s * NH + head) * HD + c4);
        float* d = Qstage + row * KPAD + c4;
        d[0] = __uint_as_float(f2tf32(v.x));
        d[1] = __uint_as_float(f2tf32(v.y));
        d[2] = __uint_as_float(f2tf32(v.z));
        d[3] = __uint_as_float(f2tf32(v.w));
    }
    __syncthreads();
    uint32_t qf[16][4];
    {
        const float* p = Qstage + (warp * 16) * KPAD;
#pragma unroll
        for (int kt = 0; kt < 16; kt++) {
            qf[kt][0] = __float_as_uint(p[(g    ) * KPAD + kt * 8 + t    ]);
            qf[kt][1] = __float_as_uint(p[(g + 8) * KPAD + kt * 8 + t    ]);
            qf[kt][2] = __float_as_uint(p[(g    ) * KPAD + kt * 8 + t + 4]);
            qf[kt][3] = __float_as_uint(p[(g + 8) * KPAD + kt * 8 + t + 4]);
        }
    }
    __syncthreads();   // all reads done before K/V overwrite

    float o_acc[16][4];
#pragma unroll
    for (int nt = 0; nt < 16; nt++)
#pragma unroll
        for (int r = 0; r < 4; r++) o_acc[nt][r] = 0.f;
    float m0 = -1e30f, m1 = -1e30f, l0 = 0.f, l1 = 0.f;   // rows g, g+8
    const float scale = 0.08838834764831845f;

    for (int k0 = 0; k0 < S_LEN; k0 += 64) {
        // ---- load K,V tiles ----
#pragma unroll
        for (int it = 0; it < 8; it++) {
            int f4 = it * 256 + tid;         // 0..2047
            int row = f4 >> 5, c4 = (f4 & 31) * 4;
            int s = k0 + row;
            float4 kv = make_float4(0.f, 0.f, 0.f, 0.f);
            float4 vv = make_float4(0.f, 0.f, 0.f, 0.f);
            if (s < S_LEN) {
                size_t off = ((size_t)s * NH + head) * HD + c4;
                kv = *(const float4*)(RK + off);
                vv = *(const float4*)(V + off);
            }
            float* dk = Ks + row * KPAD + c4;
            dk[0] = __uint_as_float(f2tf32(kv.x));
            dk[1] = __uint_as_float(f2tf32(kv.y));
            dk[2] = __uint_as_float(f2tf32(kv.z));
            dk[3] = __uint_as_float(f2tf32(kv.w));
            float* dv = Vs + row * KPAD + c4;
            dv[0] = __uint_as_float(f2tf32(vv.x));
            dv[1] = __uint_as_float(f2tf32(vv.y));
            dv[2] = __uint_as_float(f2tf32(vv.z));
            dv[3] = __uint_as_float(f2tf32(vv.w));
        }
        __syncthreads();

        // ---- scores: S[m16][n64] per warp ----
        float sf[8][4];
#pragma unroll
        for (int nt = 0; nt < 8; nt++)
#pragma unroll
            for (int r = 0; r < 4; r++) sf[nt][r] = 0.f;
#pragma unroll
        for (int kt = 0; kt < 16; kt++) {
#pragma unroll
            for (int nt = 0; nt < 8; nt++) {
                const float* p = Ks + (nt * 8 + g) * KPAD + kt * 8;
                uint32_t b0 = __float_as_uint(p[t]);
                uint32_t b1 = __float_as_uint(p[t + 4]);
                mma_tf32(sf[nt], qf[kt][0], qf[kt][1], qf[kt][2], qf[kt][3], b0, b1);
            }
        }
        // scale + mask
        bool edge = (k0 + 64 > S_LEN);
#pragma unroll
        for (int nt = 0; nt < 8; nt++) {
#pragma unroll
            for (int r = 0; r < 4; r++) sf[nt][r] *= scale;
            if (edge) {
                int col = k0 + nt * 8 + 2 * t;
                if (col     >= S_LEN) { sf[nt][0] = -1e30f; sf[nt][2] = -1e30f; }
                if (col + 1 >= S_LEN) { sf[nt][1] = -1e30f; sf[nt][3] = -1e30f; }
            }
        }
        // ---- online softmax (rows g and g+8, quad-shared) ----
        float mx0 = -1e30f, mx1 = -1e30f;
#pragma unroll
        for (int nt = 0; nt < 8; nt++) {
            mx0 = fmaxf(mx0, fmaxf(sf[nt][0], sf[nt][1]));
            mx1 = fmaxf(mx1, fmaxf(sf[nt][2], sf[nt][3]));
        }
        mx0 = fmaxf(mx0, __shfl_xor_sync(0xffffffffu, mx0, 1));
        mx0 = fmaxf(mx0, __shfl_xor_sync(0xffffffffu, mx0, 2));
        mx1 = fmaxf(mx1, __shfl_xor_sync(0xffffffffu, mx1, 1));
        mx1 = fmaxf(mx1, __shfl_xor_sync(0xffffffffu, mx1, 2));
        float mn0 = fmaxf(m0, mx0), mn1 = fmaxf(m1, mx1);
        float c0 = __expf(m0 - mn0), c1 = __expf(m1 - mn1);
        float s0 = 0.f, s1 = 0.f;
#pragma unroll
        for (int nt = 0; nt < 8; nt++) {
            sf[nt][0] = __expf(sf[nt][0] - mn0);
            sf[nt][1] = __expf(sf[nt][1] - mn0);
            sf[nt][2] = __expf(sf[nt][2] - mn1);
            sf[nt][3] = __expf(sf[nt][3] - mn1);
            s0 += sf[nt][0] + sf[nt][1];
            s1 += sf[nt][2] + sf[nt][3];
        }
        s0 += __shfl_xor_sync(0xffffffffu, s0, 1);
        s0 += __shfl_xor_sync(0xffffffffu, s0, 2);
        s1 += __shfl_xor_sync(0xffffffffu, s1, 1);
        s1 += __shfl_xor_sync(0xffffffffu, s1, 2);
        l0 = l0 * c0 + s0;  l1 = l1 * c1 + s1;
        m0 = mn0;  m1 = mn1;
#pragma unroll
        for (int nt = 0; nt < 16; nt++) {
            o_acc[nt][0] *= c0; o_acc[nt][1] *= c0;
            o_acc[nt][2] *= c1; o_acc[nt][3] *= c1;
        }
        // ---- write P (tf32) to smem: rows warp*16+{g,g+8}, cols nt*8+2t{,+1} ----
        {
            float* pr0 = Ps + (warp * 16 + g    ) * PPAD;
            float* pr1 = Ps + (warp * 16 + g + 8) * PPAD;
#pragma unroll
            for (int nt = 0; nt < 8; nt++) {
                int col = nt * 8 + 2 * t;
                pr0[col    ] = __uint_as_float(f2tf32(sf[nt][0]));
                pr0[col + 1] = __uint_as_float(f2tf32(sf[nt][1]));
                pr1[col    ] = __uint_as_float(f2tf32(sf[nt][2]));
                pr1[col + 1] = __uint_as_float(f2tf32(sf[nt][3]));
            }
        }
        __syncwarp();   // each warp reads only its own 16 P-rows

        // ---- O += P @ V ----
#pragma unroll
        for (int kt = 0; kt < 8; kt++) {
            const float* pp = Ps + (warp * 16) * PPAD + kt * 8;
            uint32_t a0 = __float_as_uint(pp[(g    ) * PPAD + t    ]);
            uint32_t a1 = __float_as_uint(pp[(g + 8) * PPAD + t    ]);
            uint32_t a2 = __float_as_uint(pp[(g    ) * PPAD + t + 4]);
            uint32_t a3 = __float_as_uint(pp[(g + 8) * PPAD + t + 4]);
#pragma unroll
            for (int nt = 0; nt < 16; nt++) {
                const float* vp = Vs + (kt * 8) * KPAD + nt * 8 + g;
                uint32_t b0 = __float_as_uint(vp[t * KPAD]);
                uint32_t b1 = __float_as_uint(vp[(t + 4) * KPAD]);
                mma_tf32(o_acc[nt], a0, a1, a2, a3, b0, b1);
            }
        }
        __syncthreads();   // done with Ks/Vs before next overwrite
    }

    // ---- write out ----
    float inv0 = 1.f / l0, inv1 = 1.f / l1;
    int s0r = q0 + warp * 16 + g;
    int s1r = s0r + 8;
#pragma unroll
    for (int nt = 0; nt < 16; nt++) {
        int col = nt * 8 + 2 * t;
        if (s0r < S_LEN) {
            float2 o = make_float2(o_acc[nt][0] * inv0, o_acc[nt][1] * inv0);
            *(float2*)(XL + ((size_t)s0r * NH + head) * HD + col) = o;
        }
        if (s1r < S_LEN) {
            float2 o = make_float2(o_acc[nt][2] * inv1, o_acc[nt][3] * inv1);
            *(float2*)(XL + ((size_t)s1r * NH + head) * HD + col) = o;
        }
    }
}

// ---------------- launch ----------------
extern "C" void kernel_launch(void* const* d_in, const int* in_sizes, int n_in,
                              void* d_out, int out_size) {
    const float* x    = (const float*)d_in[0];
    const float* freqs= (const float*)d_in[1];
    const float* gkm  = (const float*)d_in[2];
    const float* gkv  = (const float*)d_in[3];
    const float* Wq   = (const float*)d_in[4];
    const float* bq   = (const float*)d_in[5];
    const float* Wk   = (const float*)d_in[6];
    const float* bk   = (const float*)d_in[7];
    const float* Wv   = (const float*)d_in[8];
    const float* bv   = (const float*)d_in[9];
    const float* Wo   = (const float*)d_in[10];
    const float* bo   = (const float*)d_in[11];
    const float* gq   = (const float*)d_in[12];
    const float* gk   = (const float*)d_in[13];
    const float* Wlin = (const float*)d_in[14];
    const float* blin = (const float*)d_in[15];
    float* out = (float*)d_out;

    float *Qp, *Kp, *Vp, *RQp, *RKp, *XLp, *Zp, *G2p, *WTp;
    cudaGetSymbolAddress((void**)&Qp,  g_Q);
    cudaGetSymbolAddress((void**)&Kp,  g_K);
    cudaGetSymbolAddress((void**)&Vp,  g_V);
    cudaGetSymbolAddress((void**)&RQp, g_RQ);
    cudaGetSymbolAddress((void**)&RKp, g_RK);
    cudaGetSymbolAddress((void**)&XLp, g_XL);
    cudaGetSymbolAddress((void**)&Zp,  g_Z);
    cudaGetSymbolAddress((void**)&G2p, g_G2);
    cudaGetSymbolAddress((void**)&WTp, g_WT);

    cudaFuncSetAttribute(attn_tc_kernel, cudaFuncAttributeMaxDynamicSharedMemorySize, ATT_SMEM);

    dim3 gemm_grid(DIM / 128, (S_LEN + 127) / 128);
    gemm_tc_kernel<<<gemm_grid, 256>>>(x, Wq, bq, Qp, S_LEN, DIM, DIM);
    gemm_tc_kernel<<<gemm_grid, 256>>>(x, Wk, bk, Kp, S_LEN, DIM, DIM);
    gemm_tc_kernel<<<gemm_grid, 256>>>(x, Wv, bv, Vp, S_LEN, DIM, DIM);
    rmsnorm_kernel<<<S_LEN, 256>>>(Qp, gq);
    rmsnorm_kernel<<<S_LEN, 256>>>(Kp, gk);
    {
        int warps = S_LEN * NH;
        int blocks = (warps * 32 + 255) / 256;
        z_kernel<<<blocks, 256>>>(Qp, gkm, Zp);
    }
    {
        int total = S_LEN * NH * 64;
        rope_kernel<<<(total + 255) / 256, 256>>>(Qp, RQp, freqs);
        rope_kernel<<<(total + 255) / 256, 256>>>(Kp, RKp, freqs);
    }
    transpose128_kernel<<<HD, HD>>>(Wlin, WTp);
    g2_kernel<<<NH * HD, HD>>>(gkv, WTp, G2p);
    {
        dim3 grid((S_LEN + 127) / 128, NH);
        attn_tc_kernel<<<grid, 256, ATT_SMEM>>>(RQp, RKp, Vp, XLp);
    }
    xg_kernel<<<S_LEN * NH, HD>>>(RQp, G2p, Zp, blin, XLp);
    gemm_tc_kernel<<<gemm_grid, 256>>>(XLp, Wo, bo, out, S_LEN, DIM, DIM);
}

// round 4
// speedup vs baseline: 14.9261x; 1.6266x over previous
#include <cuda_runtime.h>
#include <cuda_fp16.h>
#include <math.h>
#include <stdint.h>

#define S_LEN 4680
#define DIM 1536
#define NH 12
#define HD 128

// ---------------- static scratch ----------------
__device__ float g_Q [S_LEN*DIM];
__device__ float g_K [S_LEN*DIM];
__device__ float g_V [S_LEN*DIM];
__device__ float g_RQ[S_LEN*DIM];
__device__ float g_RK[S_LEN*DIM];
__device__ float g_XL[S_LEN*DIM];
__device__ float g_Z [S_LEN*NH];
__device__ float g_G2[NH*HD*HD];
__device__ float g_WT[HD*HD];

// ---------------- helpers ----------------
__device__ __forceinline__ uint32_t pack_h2(float lo, float hi) {
    __half2 h = __floats2half2_rn(lo, hi);
    return *reinterpret_cast<uint32_t*>(&h);
}
__device__ __forceinline__ void mma_f16(float c[4],
                                        uint32_t a0, uint32_t a1, uint32_t a2, uint32_t a3,
                                        uint32_t b0, uint32_t b1) {
    asm("mma.sync.aligned.m16n8k16.row.col.f32.f16.f16.f32 "
        "{%0,%1,%2,%3},{%4,%5,%6,%7},{%8,%9},{%0,%1,%2,%3};"
        : "+f"(c[0]), "+f"(c[1]), "+f"(c[2]), "+f"(c[3])
        : "r"(a0), "r"(a1), "r"(a2), "r"(a3), "r"(b0), "r"(b1));
}
__device__ __forceinline__ void ldmx4t(uint32_t &r0, uint32_t &r1, uint32_t &r2, uint32_t &r3,
                                       const __half* p) {
    uint32_t addr = (uint32_t)__cvta_generic_to_shared(p);
    asm volatile("ldmatrix.sync.aligned.m8n8.x4.trans.shared.b16 {%0,%1,%2,%3},[%4];"
                 : "=r"(r0), "=r"(r1), "=r"(r2), "=r"(r3) : "r"(addr));
}

// ---------------- FP16 GEMM: C[M,N] = A[M,K] @ W[N,K]^T + bias ----------------
// 128x128x64 tiles, 256 thr / 8 warps (2m x 4n), warp tile 64x32.
#define GKP 72
__global__ __launch_bounds__(256) void gemm_h_kernel(
    const float* __restrict__ A, const float* __restrict__ W,
    const float* __restrict__ bias, float* __restrict__ C,
    int M, int N, int K) {
    __shared__ __half As[128 * GKP];
    __shared__ __half Bs[128 * GKP];
    const int tid = threadIdx.x;
    const int warp = tid >> 5, lane = tid & 31;
    const int g = lane >> 2, t = lane & 3;
    const int wm = warp >> 2, wn = warp & 3;
    const int bm = blockIdx.y * 128, bn = blockIdx.x * 128;

    float acc[4][4][4];
#pragma unroll
    for (int i = 0; i < 4; i++)
#pragma unroll
        for (int j = 0; j < 4; j++)
#pragma unroll
            for (int r = 0; r < 4; r++) acc[i][j][r] = 0.f;

    for (int k0 = 0; k0 < K; k0 += 64) {
#pragma unroll
        for (int it = 0; it < 8; it++) {
            int f4 = it * 256 + tid;          // 0..2047
            int row = f4 >> 4, c4 = (f4 & 15) * 4;
            float4 v = make_float4(0.f, 0.f, 0.f, 0.f);
            int gm = bm + row;
            if (gm < M) v = *(const float4*)(A + (size_t)gm * K + k0 + c4);
            *(uint2*)&As[row * GKP + c4] = make_uint2(pack_h2(v.x, v.y), pack_h2(v.z, v.w));
            float4 w = *(const float4*)(W + (size_t)(bn + row) * K + k0 + c4);
            *(uint2*)&Bs[row * GKP + c4] = make_uint2(pack_h2(w.x, w.y), pack_h2(w.z, w.w));
        }
        __syncthreads();
#pragma unroll
        for (int ks = 0; ks < 4; ks++) {
            int kk = ks * 16;
            uint32_t af[4][4], bf[4][2];
#pragma unroll
            for (int mt = 0; mt < 4; mt++) {
                const __half* p = As + (wm * 64 + mt * 16) * GKP + kk + 2 * t;
                af[mt][0] = *(const uint32_t*)(p + (g    ) * GKP);
                af[mt][1] = *(const uint32_t*)(p + (g + 8) * GKP);
                af[mt][2] = *(const uint32_t*)(p + (g    ) * GKP + 8);
                af[mt][3] = *(const uint32_t*)(p + (g + 8) * GKP + 8);
            }
#pragma unroll
            for (int nt = 0; nt < 4; nt++) {
                const __half* p = Bs + (wn * 32 + nt * 8 + g) * GKP + kk + 2 * t;
                bf[nt][0] = *(const uint32_t*)(p);
                bf[nt][1] = *(const uint32_t*)(p + 8);
            }
#pragma unroll
            for (int mt = 0; mt < 4; mt++)
#pragma unroll
                for (int nt = 0; nt < 4; nt++)
                    mma_f16(acc[mt][nt], af[mt][0], af[mt][1], af[mt][2], af[mt][3],
                            bf[nt][0], bf[nt][1]);
        }
        __syncthreads();
    }
#pragma unroll
    for (int mt = 0; mt < 4; mt++) {
#pragma unroll
        for (int nt = 0; nt < 4; nt++) {
            int col = bn + wn * 32 + nt * 8 + 2 * t;
            float2 b2 = *(const float2*)(bias + col);
            int r0 = bm + wm * 64 + mt * 16 + g;
            int r1 = r0 + 8;
            if (r0 < M) {
                float2 o = make_float2(acc[mt][nt][0] + b2.x, acc[mt][nt][1] + b2.y);
                *(float2*)(C + (size_t)r0 * N + col) = o;
            }
            if (r1 < M) {
                float2 o = make_float2(acc[mt][nt][2] + b2.x, acc[mt][nt][3] + b2.y);
                *(float2*)(C + (size_t)r1 * N + col) = o;
            }
        }
    }
}

// ---------------- RMSNorm ----------------
__global__ void rmsnorm_kernel(float* __restrict__ X, const float* __restrict__ gw) {
    int row = blockIdx.x;
    float* x = X + (size_t)row * DIM;
    float ss = 0.f;
    for (int i = threadIdx.x; i < DIM; i += 256) { float v = x[i]; ss += v * v; }
    __shared__ float red[8];
    __shared__ float s_scale;
    int lane = threadIdx.x & 31, wid = threadIdx.x >> 5;
#pragma unroll
    for (int o = 16; o > 0; o >>= 1) ss += __shfl_xor_sync(0xffffffffu, ss, o);
    if (lane == 0) red[wid] = ss;
    __syncthreads();
    if (wid == 0) {
        float v = (lane < 8) ? red[lane] : 0.f;
#pragma unroll
        for (int o = 4; o > 0; o >>= 1) v += __shfl_xor_sync(0xffffffffu, v, o);
        if (lane == 0) s_scale = rsqrtf(v / (float)DIM + 1e-6f);
    }
    __syncthreads();
    float sc = s_scale;
    for (int i = threadIdx.x; i < DIM; i += 256) x[i] = x[i] * sc * gw[i];
}

// ---------------- z ----------------
__global__ void z_kernel(const float* __restrict__ Q, const float* __restrict__ gkm,
                         float* __restrict__ Z) {
    int idx = (blockIdx.x * blockDim.x + threadIdx.x) >> 5;
    if (idx >= S_LEN * NH) return;
    int lane = threadIdx.x & 31;
    int n = idx % NH;
    const float* q = Q + (size_t)idx * HD;
    float sum = 0.f;
#pragma unroll
    for (int d = lane; d < HD; d += 32) sum += fmaxf(q[d], 0.f) * gkm[n * HD + d];
#pragma unroll
    for (int o = 16; o > 0; o >>= 1) sum += __shfl_xor_sync(0xffffffffu, sum, o);
    if (lane == 0) Z[idx] = 1.f / (sum + 1e-6f);
}

// ---------------- RoPE ----------------
__global__ void rope_kernel(const float* __restrict__ X, float* __restrict__ Y,
                            const float* __restrict__ freqs) {
    int gid = blockIdx.x * blockDim.x + threadIdx.x;
    const int total = S_LEN * NH * 64;
    if (gid >= total) return;
    int i = gid & 63;
    int sn = gid >> 6;
    int s = sn / NH;
    int w = s % 52;
    int h = (s / 52) % 30;
    int f = s / (52 * 30);
    int pos;
    if (i < 22) pos = f; else if (i < 43) pos = h; else pos = w;
    float cr = freqs[(pos * 64 + i) * 2 + 0];
    float ci = freqs[(pos * 64 + i) * 2 + 1];
    size_t base = (size_t)sn * HD + 2 * i;
    float xr = X[base], xi = X[base + 1];
    Y[base]     = xr * cr - xi * ci;
    Y[base + 1] = xr * ci + xi * cr;
}

// ---------------- Wlin transpose ----------------
__global__ void transpose128_kernel(const float* __restrict__ in, float* __restrict__ out) {
    int j = blockIdx.x, m = threadIdx.x;
    out[m * HD + j] = in[j * HD + m];
}

// ---------------- G2 = g_kv @ Wlin^T ----------------
__global__ void g2_kernel(const float* __restrict__ gkv, const float* __restrict__ WT,
                          float* __restrict__ G2) {
    int nd = blockIdx.x;
    __shared__ float kv[HD];
    kv[threadIdx.x] = gkv[(size_t)nd * HD + threadIdx.x];
    __syncthreads();
    int j = threadIdx.x;
    float sum = 0.f;
#pragma unroll 8
    for (int m = 0; m < HD; m++) sum += kv[m] * WT[m * HD + j];
    G2[(size_t)nd * HD + j] = sum;
}

// ---------------- XL += z*(rq@G2) + blin ----------------
__global__ void xg_kernel(const float* __restrict__ RQ, const float* __restrict__ G2,
                          const float* __restrict__ Z, const float* __restrict__ blin,
                          float* __restrict__ XL) {
    int sn = blockIdx.x;
    int n = sn % NH;
    int j = threadIdx.x;
    __shared__ float rq[HD];
    rq[j] = RQ[(size_t)sn * HD + j];
    __syncthreads();
    const float* g2 = G2 + (size_t)n * HD * HD;
    float sum = 0.f;
#pragma unroll 8
    for (int d = 0; d < HD; d++) sum += rq[d] * g2[d * HD + j];
    XL[(size_t)sn * HD + j] += sum * Z[sn] + blin[j];
}

// ---------------- FP16 flash attention ----------------
// Br=128 (8 warps x m16), Bc=64, HD=128. P register-resident.
// smem halves: Ks[64*136] Vs[64*136]; Q staged into same region.
#define KPH 136
#define ATT_SMEM (128 * KPH * 2)
__global__ __launch_bounds__(256, 1) void attn_h_kernel(
    const float* __restrict__ RQ, const float* __restrict__ RK,
    const float* __restrict__ V, float* __restrict__ XL) {
    extern __shared__ __half smh[];
    __half* Ks = smh;
    __half* Vs = smh + 64 * KPH;
    __half* Qs = smh;   // aliases Ks+Vs (128*KPH)

    const int tid = threadIdx.x;
    const int warp = tid >> 5, lane = tid & 31;
    const int g = lane >> 2, t = lane & 3;
    const int head = blockIdx.y;
    const int q0 = blockIdx.x * 128;

    // ---- stage Q tile (128x128) as fp16 ----
#pragma unroll
    for (int it = 0; it < 16; it++) {
        int f4 = it * 256 + tid;            // 0..4095
        int row = f4 >> 5, c4 = (f4 & 31) * 4;
        int s = q0 + row;
        float4 v = make_float4(0.f, 0.f, 0.f, 0.f);
        if (s < S_LEN) v = *(const float4*)(RQ + ((size_t)s * NH + head) * HD + c4);
        *(uint2*)&Qs[row * KPH + c4] = make_uint2(pack_h2(v.x, v.y), pack_h2(v.z, v.w));
    }
    __syncthreads();
    uint32_t qf[8][4];
    {
        const __half* p = Qs + (warp * 16) * KPH + 2 * t;
#pragma unroll
        for (int kt = 0; kt < 8; kt++) {
            int kk = kt * 16;
            qf[kt][0] = *(const uint32_t*)(p + (g    ) * KPH + kk);
            qf[kt][1] = *(const uint32_t*)(p + (g + 8) * KPH + kk);
            qf[kt][2] = *(const uint32_t*)(p + (g    ) * KPH + kk + 8);
            qf[kt][3] = *(const uint32_t*)(p + (g + 8) * KPH + kk + 8);
        }
    }
    __syncthreads();   // Q reads done before K/V overwrite

    float o_acc[16][4];
#pragma unroll
    for (int nt = 0; nt < 16; nt++)
#pragma unroll
        for (int r = 0; r < 4; r++) o_acc[nt][r] = 0.f;
    float m0 = -1e30f, m1 = -1e30f, l0 = 0.f, l1 = 0.f;
    const float scale = 0.08838834764831845f;

    for (int k0 = 0; k0 < S_LEN; k0 += 64) {
        // ---- load K,V tiles as fp16 ----
#pragma unroll
        for (int it = 0; it < 8; it++) {
            int f4 = it * 256 + tid;         // 0..2047
            int row = f4 >> 5, c4 = (f4 & 31) * 4;
            int s = k0 + row;
            float4 kv = make_float4(0.f, 0.f, 0.f, 0.f);
            float4 vv = make_float4(0.f, 0.f, 0.f, 0.f);
            if (s < S_LEN) {
                size_t off = ((size_t)s * NH + head) * HD + c4;
                kv = *(const float4*)(RK + off);
                vv = *(const float4*)(V + off);
            }
            *(uint2*)&Ks[row * KPH + c4] = make_uint2(pack_h2(kv.x, kv.y), pack_h2(kv.z, kv.w));
            *(uint2*)&Vs[row * KPH + c4] = make_uint2(pack_h2(vv.x, vv.y), pack_h2(vv.z, vv.w));
        }
        __syncthreads();

        // ---- scores S[m16][n64] per warp ----
        float sf[8][4];
#pragma unroll
        for (int nt = 0; nt < 8; nt++)
#pragma unroll
            for (int r = 0; r < 4; r++) sf[nt][r] = 0.f;
#pragma unroll
        for (int kt = 0; kt < 8; kt++) {
            int kk = kt * 16 + 2 * t;
#pragma unroll
            for (int nt = 0; nt < 8; nt++) {
                const __half* p = Ks + (nt * 8 + g) * KPH + kk;
                uint32_t b0 = *(const uint32_t*)(p);
                uint32_t b1 = *(const uint32_t*)(p + 8);
                mma_f16(sf[nt], qf[kt][0], qf[kt][1], qf[kt][2], qf[kt][3], b0, b1);
            }
        }
        // scale + mask
        bool edge = (k0 + 64 > S_LEN);
#pragma unroll
        for (int nt = 0; nt < 8; nt++) {
#pragma unroll
            for (int r = 0; r < 4; r++) sf[nt][r] *= scale;
            if (edge) {
                int col = k0 + nt * 8 + 2 * t;
                if (col     >= S_LEN) { sf[nt][0] = -1e30f; sf[nt][2] = -1e30f; }
                if (col + 1 >= S_LEN) { sf[nt][1] = -1e30f; sf[nt][3] = -1e30f; }
            }
        }
        // ---- online softmax (rows g, g+8 shared within quad) ----
        float mx0 = -1e30f, mx1 = -1e30f;
#pragma unroll
        for (int nt = 0; nt < 8; nt++) {
            mx0 = fmaxf(mx0, fmaxf(sf[nt][0], sf[nt][1]));
            mx1 = fmaxf(mx1, fmaxf(sf[nt][2], sf[nt][3]));
        }
        mx0 = fmaxf(mx0, __shfl_xor_sync(0xffffffffu, mx0, 1));
        mx0 = fmaxf(mx0, __shfl_xor_sync(0xffffffffu, mx0, 2));
        mx1 = fmaxf(mx1, __shfl_xor_sync(0xffffffffu, mx1, 1));
        mx1 = fmaxf(mx1, __shfl_xor_sync(0xffffffffu, mx1, 2));
        float mn0 = fmaxf(m0, mx0), mn1 = fmaxf(m1, mx1);
        float c0 = __expf(m0 - mn0), c1 = __expf(m1 - mn1);
        float s0 = 0.f, s1 = 0.f;
#pragma unroll
        for (int nt = 0; nt < 8; nt++) {
            sf[nt][0] = __expf(sf[nt][0] - mn0);
            sf[nt][1] = __expf(sf[nt][1] - mn0);
            sf[nt][2] = __expf(sf[nt][2] - mn1);
            sf[nt][3] = __expf(sf[nt][3] - mn1);
            s0 += sf[nt][0] + sf[nt][1];
            s1 += sf[nt][2] + sf[nt][3];
        }
        s0 += __shfl_xor_sync(0xffffffffu, s0, 1);
        s0 += __shfl_xor_sync(0xffffffffu, s0, 2);
        s1 += __shfl_xor_sync(0xffffffffu, s1, 1);
        s1 += __shfl_xor_sync(0xffffffffu, s1, 2);
        l0 = l0 * c0 + s0;  l1 = l1 * c1 + s1;
        m0 = mn0;  m1 = mn1;
#pragma unroll
        for (int nt = 0; nt < 16; nt++) {
            o_acc[nt][0] *= c0; o_acc[nt][1] *= c0;
            o_acc[nt][2] *= c1; o_acc[nt][3] *= c1;
        }
        // ---- O += P @ V, P register-resident ----
        const int vr = lane & 7, vq = lane >> 3;
#pragma unroll
        for (int kt = 0; kt < 4; kt++) {
            uint32_t a0 = pack_h2(sf[2*kt  ][0], sf[2*kt  ][1]);
            uint32_t a1 = pack_h2(sf[2*kt  ][2], sf[2*kt  ][3]);
            uint32_t a2 = pack_h2(sf[2*kt+1][0], sf[2*kt+1][1]);
            uint32_t a3 = pack_h2(sf[2*kt+1][2], sf[2*kt+1][3]);
#pragma unroll
            for (int nb = 0; nb < 8; nb++) {
                const __half* vp = Vs + (kt * 16 + (vq & 1) * 8 + vr) * KPH
                                      + nb * 16 + (vq >> 1) * 8;
                uint32_t v0, v1, v2, v3;
                ldmx4t(v0, v1, v2, v3, vp);
                mma_f16(o_acc[2*nb    ], a0, a1, a2, a3, v0, v1);
                mma_f16(o_acc[2*nb + 1], a0, a1, a2, a3, v2, v3);
            }
        }
        __syncthreads();
    }

    float inv0 = 1.f / l0, inv1 = 1.f / l1;
    int s0r = q0 + warp * 16 + g;
    int s1r = s0r + 8;
#pragma unroll
    for (int nt = 0; nt < 16; nt++) {
        int col = nt * 8 + 2 * t;
        if (s0r < S_LEN) {
            float2 o = make_float2(o_acc[nt][0] * inv0, o_acc[nt][1] * inv0);
            *(float2*)(XL + ((size_t)s0r * NH + head) * HD + col) = o;
        }
        if (s1r < S_LEN) {
            float2 o = make_float2(o_acc[nt][2] * inv1, o_acc[nt][3] * inv1);
            *(float2*)(XL + ((size_t)s1r * NH + head) * HD + col) = o;
        }
    }
}

// ---------------- launch ----------------
extern "C" void kernel_launch(void* const* d_in, const int* in_sizes, int n_in,
                              void* d_out, int out_size) {
    const float* x    = (const float*)d_in[0];
    const float* freqs= (const float*)d_in[1];
    const float* gkm  = (const float*)d_in[2];
    const float* gkv  = (const float*)d_in[3];
    const float* Wq   = (const float*)d_in[4];
    const float* bq   = (const float*)d_in[5];
    const float* Wk   = (const float*)d_in[6];
    const float* bk   = (const float*)d_in[7];
    const float* Wv   = (const float*)d_in[8];
    const float* bv   = (const float*)d_in[9];
    const float* Wo   = (const float*)d_in[10];
    const float* bo   = (const float*)d_in[11];
    const float* gq   = (const float*)d_in[12];
    const float* gk   = (const float*)d_in[13];
    const float* Wlin = (const float*)d_in[14];
    const float* blin = (const float*)d_in[15];
    float* out = (float*)d_out;

    float *Qp, *Kp, *Vp, *RQp, *RKp, *XLp, *Zp, *G2p, *WTp;
    cudaGetSymbolAddress((void**)&Qp,  g_Q);
    cudaGetSymbolAddress((void**)&Kp,  g_K);
    cudaGetSymbolAddress((void**)&Vp,  g_V);
    cudaGetSymbolAddress((void**)&RQp, g_RQ);
    cudaGetSymbolAddress((void**)&RKp, g_RK);
    cudaGetSymbolAddress((void**)&XLp, g_XL);
    cudaGetSymbolAddress((void**)&Zp,  g_Z);
    cudaGetSymbolAddress((void**)&G2p, g_G2);
    cudaGetSymbolAddress((void**)&WTp, g_WT);

    cudaFuncSetAttribute(attn_h_kernel, cudaFuncAttributeMaxDynamicSharedMemorySize, ATT_SMEM);

    dim3 gemm_grid(DIM / 128, (S_LEN + 127) / 128);
    gemm_h_kernel<<<gemm_grid, 256>>>(x, Wq, bq, Qp, S_LEN, DIM, DIM);
    gemm_h_kernel<<<gemm_grid, 256>>>(x, Wk, bk, Kp, S_LEN, DIM, DIM);
    gemm_h_kernel<<<gemm_grid, 256>>>(x, Wv, bv, Vp, S_LEN, DIM, DIM);
    rmsnorm_kernel<<<S_LEN, 256>>>(Qp, gq);
    rmsnorm_kernel<<<S_LEN, 256>>>(Kp, gk);
    {
        int warps = S_LEN * NH;
        int blocks = (warps * 32 + 255) / 256;
        z_kernel<<<blocks, 256>>>(Qp, gkm, Zp);
    }
    {
        int total = S_LEN * NH * 64;
        rope_kernel<<<(total + 255) / 256, 256>>>(Qp, RQp, freqs);
        rope_kernel<<<(total + 255) / 256, 256>>>(Kp, RKp, freqs);
    }
    transpose128_kernel<<<HD, HD>>>(Wlin, WTp);
    g2_kernel<<<NH * HD, HD>>>(gkv, WTp, G2p);
    {
        dim3 grid((S_LEN + 127) / 128, NH);
        attn_h_kernel<<<grid, 256, ATT_SMEM>>>(RQp, RKp, Vp, XLp);
    }
    xg_kernel<<<S_LEN * NH, HD>>>(RQp, G2p, Zp, blin, XLp);
    gemm_h_kernel<<<gemm_grid, 256>>>(XLp, Wo, bo, out, S_LEN, DIM, DIM);
}

// round 5
// speedup vs baseline: 23.6006x; 1.5812x over previous
#include <cuda_runtime.h>
#include <cuda_fp16.h>
#include <math.h>
#include <stdint.h>

#define S_LEN 4680
#define DIM 1536
#define NH 12
#define HD 128

// ---------------- static scratch ----------------
__device__ float  g_Q  [S_LEN*DIM];
__device__ float  g_K  [S_LEN*DIM];
__device__ float  g_RQ [S_LEN*DIM];
__device__ float  g_XL [S_LEN*DIM];
__device__ float  g_Z  [S_LEN*NH];
__device__ float  g_WT [HD*HD];
__device__ __half g_xh [S_LEN*DIM];
__device__ __half g_Wqh[DIM*DIM];
__device__ __half g_Wkh[DIM*DIM];
__device__ __half g_Wvh[DIM*DIM];
__device__ __half g_Woh[DIM*DIM];
__device__ __half g_Vh [S_LEN*DIM];
__device__ __half g_RQh[S_LEN*DIM];
__device__ __half g_RKh[S_LEN*DIM];
__device__ __half g_XLh[S_LEN*DIM];
__device__ __half g_G2h[NH*HD*HD];   // [n][j][d]

// ---------------- helpers ----------------
__device__ __forceinline__ uint32_t pack_h2(float lo, float hi) {
    __half2 h = __floats2half2_rn(lo, hi);
    return *reinterpret_cast<uint32_t*>(&h);
}
__device__ __forceinline__ void mma_f16(float c[4],
                                        uint32_t a0, uint32_t a1, uint32_t a2, uint32_t a3,
                                        uint32_t b0, uint32_t b1) {
    asm("mma.sync.aligned.m16n8k16.row.col.f32.f16.f16.f32 "
        "{%0,%1,%2,%3},{%4,%5,%6,%7},{%8,%9},{%0,%1,%2,%3};"
        : "+f"(c[0]), "+f"(c[1]), "+f"(c[2]), "+f"(c[3])
        : "r"(a0), "r"(a1), "r"(a2), "r"(a3), "r"(b0), "r"(b1));
}
__device__ __forceinline__ void ldmx4t(uint32_t &r0, uint32_t &r1, uint32_t &r2, uint32_t &r3,
                                       const __half* p) {
    uint32_t addr = (uint32_t)__cvta_generic_to_shared(p);
    asm volatile("ldmatrix.sync.aligned.m8n8.x4.trans.shared.b16 {%0,%1,%2,%3},[%4];"
                 : "=r"(r0), "=r"(r1), "=r"(r2), "=r"(r3) : "r"(addr));
}
__device__ __forceinline__ void cp16(__half* dst, const __half* src, int src_bytes) {
    uint32_t d = (uint32_t)__cvta_generic_to_shared(dst);
    asm volatile("cp.async.cg.shared.global [%0], [%1], 16, %2;"
                 :: "r"(d), "l"(src), "r"(src_bytes));
}
#define CP_COMMIT() asm volatile("cp.async.commit_group;")
#define CP_WAIT0()  asm volatile("cp.async.wait_group 0;")

// ---------------- fp32 -> fp16 convert (n4 = #float4 chunks) ----------------
__global__ void f2h_kernel(const float* __restrict__ in, __half* __restrict__ out, int n4) {
    int i = blockIdx.x * blockDim.x + threadIdx.x;
    if (i < n4) {
        float4 v = ((const float4*)in)[i];
        ((uint2*)out)[i] = make_uint2(pack_h2(v.x, v.y), pack_h2(v.z, v.w));
    }
}

// ---------------- cp.async FP16 GEMM: C[M,N] = A @ W^T + bias ----------------
// 128x128x64 tiles, 2-stage pipeline, 8 warps (2m x 4n), warp tile 64x32.
#define GKP 72
#define GEMM_SMEM (2 * 2 * 128 * GKP * 2)   // 2 stages x (A+B) x 128*GKP halves x 2B
template<bool HALF_OUT>
__global__ __launch_bounds__(256) void gemm_async_kernel(
    const __half* __restrict__ A, const __half* __restrict__ W,
    const float* __restrict__ bias, void* __restrict__ Cout,
    int M, int N, int K) {
    extern __shared__ __half gsm[];
    const int STG = 2 * 128 * GKP;
    const int tid = threadIdx.x;
    const int warp = tid >> 5, lane = tid & 31;
    const int g = lane >> 2, t = lane & 3;
    const int wm = warp >> 2, wn = warp & 3;
    const int bm = blockIdx.y * 128, bn = blockIdx.x * 128;

    float acc[4][4][4];
#pragma unroll
    for (int i = 0; i < 4; i++)
#pragma unroll
        for (int j = 0; j < 4; j++)
#pragma unroll
            for (int r = 0; r < 4; r++) acc[i][j][r] = 0.f;

    auto load_stage = [&](int s, int k0) {
        __half* As = gsm + s * STG;
        __half* Bs = As + 128 * GKP;
#pragma unroll
        for (int it = 0; it < 4; it++) {
            int f = it * 256 + tid;              // 0..1023
            int row = f >> 3, c8 = (f & 7) * 8;
            int gm = bm + row;
            const __half* sa = A + (size_t)(gm < M ? gm : M - 1) * K + k0 + c8;
            cp16(As + row * GKP + c8, sa, gm < M ? 16 : 0);
            const __half* sb = W + (size_t)(bn + row) * K + k0 + c8;
            cp16(Bs + row * GKP + c8, sb, 16);
        }
    };

    const int nT = K / 64;
    load_stage(0, 0);
    CP_COMMIT();
    for (int i = 0; i < nT; i++) {
        CP_WAIT0();
        __syncthreads();
        if (i + 1 < nT) { load_stage((i + 1) & 1, (i + 1) * 64); CP_COMMIT(); }
        const __half* As = gsm + (i & 1) * STG;
        const __half* Bs = As + 128 * GKP;
#pragma unroll
        for (int ks = 0; ks < 4; ks++) {
            int kk = ks * 16;
            uint32_t af[4][4], bf[4][2];
#pragma unroll
            for (int mt = 0; mt < 4; mt++) {
                const __half* p = As + (wm * 64 + mt * 16) * GKP + kk + 2 * t;
                af[mt][0] = *(const uint32_t*)(p + (g    ) * GKP);
                af[mt][1] = *(const uint32_t*)(p + (g + 8) * GKP);
                af[mt][2] = *(const uint32_t*)(p + (g    ) * GKP + 8);
                af[mt][3] = *(const uint32_t*)(p + (g + 8) * GKP + 8);
            }
#pragma unroll
            for (int nt = 0; nt < 4; nt++) {
                const __half* p = Bs + (wn * 32 + nt * 8 + g) * GKP + kk + 2 * t;
                bf[nt][0] = *(const uint32_t*)(p);
                bf[nt][1] = *(const uint32_t*)(p + 8);
            }
#pragma unroll
            for (int mt = 0; mt < 4; mt++)
#pragma unroll
                for (int nt = 0; nt < 4; nt++)
                    mma_f16(acc[mt][nt], af[mt][0], af[mt][1], af[mt][2], af[mt][3],
                            bf[nt][0], bf[nt][1]);
        }
        __syncthreads();
    }
#pragma unroll
    for (int mt = 0; mt < 4; mt++) {
#pragma unroll
        for (int nt = 0; nt < 4; nt++) {
            int col = bn + wn * 32 + nt * 8 + 2 * t;
            float2 b2 = *(const float2*)(bias + col);
            int r0 = bm + wm * 64 + mt * 16 + g;
            int r1 = r0 + 8;
            if (HALF_OUT) {
                __half* Ch = (__half*)Cout;
                if (r0 < M)
                    *(uint32_t*)(Ch + (size_t)r0 * N + col) =
                        pack_h2(acc[mt][nt][0] + b2.x, acc[mt][nt][1] + b2.y);
                if (r1 < M)
                    *(uint32_t*)(Ch + (size_t)r1 * N + col) =
                        pack_h2(acc[mt][nt][2] + b2.x, acc[mt][nt][3] + b2.y);
            } else {
                float* C = (float*)Cout;
                if (r0 < M)
                    *(float2*)(C + (size_t)r0 * N + col) =
                        make_float2(acc[mt][nt][0] + b2.x, acc[mt][nt][1] + b2.y);
                if (r1 < M)
                    *(float2*)(C + (size_t)r1 * N + col) =
                        make_float2(acc[mt][nt][2] + b2.x, acc[mt][nt][3] + b2.y);
            }
        }
    }
}

// ---------------- RMSNorm ----------------
__global__ void rmsnorm_kernel(float* __restrict__ X, const float* __restrict__ gw) {
    int row = blockIdx.x;
    float* x = X + (size_t)row * DIM;
    float ss = 0.f;
    for (int i = threadIdx.x; i < DIM; i += 256) { float v = x[i]; ss += v * v; }
    __shared__ float red[8];
    __shared__ float s_scale;
    int lane = threadIdx.x & 31, wid = threadIdx.x >> 5;
#pragma unroll
    for (int o = 16; o > 0; o >>= 1) ss += __shfl_xor_sync(0xffffffffu, ss, o);
    if (lane == 0) red[wid] = ss;
    __syncthreads();
    if (wid == 0) {
        float v = (lane < 8) ? red[lane] : 0.f;
#pragma unroll
        for (int o = 4; o > 0; o >>= 1) v += __shfl_xor_sync(0xffffffffu, v, o);
        if (lane == 0) s_scale = rsqrtf(v / (float)DIM + 1e-6f);
    }
    __syncthreads();
    float sc = s_scale;
    for (int i = threadIdx.x; i < DIM; i += 256) x[i] = x[i] * sc * gw[i];
}

// ---------------- z ----------------
__global__ void z_kernel(const float* __restrict__ Q, const float* __restrict__ gkm,
                         float* __restrict__ Z) {
    int idx = (blockIdx.x * blockDim.x + threadIdx.x) >> 5;
    if (idx >= S_LEN * NH) return;
    int lane = threadIdx.x & 31;
    int n = idx % NH;
    const float* q = Q + (size_t)idx * HD;
    float sum = 0.f;
#pragma unroll
    for (int d = lane; d < HD; d += 32) sum += fmaxf(q[d], 0.f) * gkm[n * HD + d];
#pragma unroll
    for (int o = 16; o > 0; o >>= 1) sum += __shfl_xor_sync(0xffffffffu, sum, o);
    if (lane == 0) Z[idx] = 1.f / (sum + 1e-6f);
}

// ---------------- RoPE (fp32 optional out + fp16 out) ----------------
__global__ void rope_kernel(const float* __restrict__ X, float* __restrict__ Yf,
                            __half* __restrict__ Yh, const float* __restrict__ freqs) {
    int gid = blockIdx.x * blockDim.x + threadIdx.x;
    const int total = S_LEN * NH * 64;
    if (gid >= total) return;
    int i = gid & 63;
    int sn = gid >> 6;
    int s = sn / NH;
    int w = s % 52;
    int h = (s / 52) % 30;
    int f = s / (52 * 30);
    int pos;
    if (i < 22) pos = f; else if (i < 43) pos = h; else pos = w;
    float cr = freqs[(pos * 64 + i) * 2 + 0];
    float ci = freqs[(pos * 64 + i) * 2 + 1];
    size_t base = (size_t)sn * HD + 2 * i;
    float xr = X[base], xi = X[base + 1];
    float yr = xr * cr - xi * ci;
    float yi = xr * ci + xi * cr;
    if (Yf) { Yf[base] = yr; Yf[base + 1] = yi; }
    *(uint32_t*)(Yh + base) = pack_h2(yr, yi);
}

// ---------------- Wlin transpose ----------------
__global__ void transpose128_kernel(const float* __restrict__ in, float* __restrict__ out) {
    int j = blockIdx.x, m = threadIdx.x;
    out[m * HD + j] = in[j * HD + m];
}

// ---------------- G2h[n][j][d] = sum_m g_kv[n,d,m] * Wlin[j,m] (half) ----------------
__global__ void g2_kernel(const float* __restrict__ gkv, const float* __restrict__ WT,
                          __half* __restrict__ G2h) {
    int nd = blockIdx.x;                // n*128 + d
    int n = nd >> 7, d = nd & 127;
    __shared__ float kv[HD];
    kv[threadIdx.x] = gkv[(size_t)nd * HD + threadIdx.x];
    __syncthreads();
    int j = threadIdx.x;
    float sum = 0.f;
#pragma unroll 8
    for (int m = 0; m < HD; m++) sum += kv[m] * WT[m * HD + j];
    G2h[((size_t)n * HD + j) * HD + d] = __float2half(sum);
}

// ---------------- xg via tensor cores: XLh = half(XL + z*(rq@G2) + blin) ----------------
#define KPH 136
#define XG_SMEM (2 * 128 * KPH * 2)
__global__ __launch_bounds__(256) void xg_mma_kernel(
    const __half* __restrict__ RQh, const __half* __restrict__ G2h,
    const float* __restrict__ Z, const float* __restrict__ blin,
    const float* __restrict__ XL, __half* __restrict__ XLh) {
    extern __shared__ __half xsm[];
    __half* RQs = xsm;
    __half* G2s = xsm + 128 * KPH;
    const int tid = threadIdx.x;
    const int warp = tid >> 5, lane = tid & 31;
    const int g = lane >> 2, t = lane & 3;
    const int head = blockIdx.y;
    const int q0 = blockIdx.x * 128;

    // load tiles
#pragma unroll
    for (int it = 0; it < 8; it++) {
        int f = it * 256 + tid;            // 0..2047
        int row = f >> 4, c8 = (f & 15) * 8;
        int s = q0 + row;
        uint4 v = make_uint4(0, 0, 0, 0);
        if (s < S_LEN) v = *(const uint4*)(RQh + ((size_t)s * NH + head) * HD + c8);
        *(uint4*)&RQs[row * KPH + c8] = v;
        uint4 gv = *(const uint4*)(G2h + ((size_t)head * HD + row) * HD + c8);
        *(uint4*)&G2s[row * KPH + c8] = gv;
    }
    __syncthreads();

    uint32_t qf[8][4];
    {
        const __half* p = RQs + (warp * 16) * KPH + 2 * t;
#pragma unroll
        for (int kt = 0; kt < 8; kt++) {
            int kk = kt * 16;
            qf[kt][0] = *(const uint32_t*)(p + (g    ) * KPH + kk);
            qf[kt][1] = *(const uint32_t*)(p + (g + 8) * KPH + kk);
            qf[kt][2] = *(const uint32_t*)(p + (g    ) * KPH + kk + 8);
            qf[kt][3] = *(const uint32_t*)(p + (g + 8) * KPH + kk + 8);
        }
    }
    float acc[16][4];
#pragma unroll
    for (int nt = 0; nt < 16; nt++)
#pragma unroll
        for (int r = 0; r < 4; r++) acc[nt][r] = 0.f;
#pragma unroll
    for (int kt = 0; kt < 8; kt++) {
        int kk = kt * 16 + 2 * t;
#pragma unroll
        for (int nt = 0; nt < 16; nt++) {
            const __half* p = G2s + (nt * 8 + g) * KPH + kk;
            uint32_t b0 = *(const uint32_t*)(p);
            uint32_t b1 = *(const uint32_t*)(p + 8);
            mma_f16(acc[nt], qf[kt][0], qf[kt][1], qf[kt][2], qf[kt][3], b0, b1);
        }
    }
    int s0r = q0 + warp * 16 + g;
    int s1r = s0r + 8;
    float z0 = (s0r < S_LEN) ? Z[s0r * NH + head] : 0.f;
    float z1 = (s1r < S_LEN) ? Z[s1r * NH + head] : 0.f;
#pragma unroll
    for (int nt = 0; nt < 16; nt++) {
        int col = nt * 8 + 2 * t;
        float2 bl = *(const float2*)(blin + col);
        if (s0r < S_LEN) {
            const float* xl = XL + ((size_t)s0r * NH + head) * HD + col;
            *(uint32_t*)(XLh + ((size_t)s0r * NH + head) * HD + col) =
                pack_h2(acc[nt][0] * z0 + bl.x + xl[0], acc[nt][1] * z0 + bl.y + xl[1]);
        }
        if (s1r < S_LEN) {
            const float* xl = XL + ((size_t)s1r * NH + head) * HD + col;
            *(uint32_t*)(XLh + ((size_t)s1r * NH + head) * HD + col) =
                pack_h2(acc[nt][2] * z1 + bl.x + xl[0], acc[nt][3] * z1 + bl.y + xl[1]);
        }
    }
}

// ---------------- FP16 flash attention, cp.async 2-stage ----------------
// Br=128 (8 warps x m16), Bc=64, HD=128, P register-resident.
#define ASTG (2 * 64 * KPH)           // halves per stage (K+V)
#define ATT_SMEM (2 * ASTG * 2)       // 2 stages, bytes
__global__ __launch_bounds__(256, 1) void attn_h_kernel(
    const __half* __restrict__ RQh, const __half* __restrict__ RKh,
    const __half* __restrict__ Vh, float* __restrict__ XL) {
    extern __shared__ __half smh[];
    const int tid = threadIdx.x;
    const int warp = tid >> 5, lane = tid & 31;
    const int g = lane >> 2, t = lane & 3;
    const int head = blockIdx.y;
    const int q0 = blockIdx.x * 128;

    // ---- stage Q (aliases stage buffers) and read fragments ----
    {
        __half* Qs = smh;
#pragma unroll
        for (int it = 0; it < 8; it++) {
            int f = it * 256 + tid;          // 0..2047
            int row = f >> 4, c8 = (f & 15) * 8;
            int s = q0 + row;
            uint4 v = make_uint4(0, 0, 0, 0);
            if (s < S_LEN) v = *(const uint4*)(RQh + ((size_t)s * NH + head) * HD + c8);
            *(uint4*)&Qs[row * KPH + c8] = v;
        }
    }
    __syncthreads();
    uint32_t qf[8][4];
    {
        const __half* p = smh + (warp * 16) * KPH + 2 * t;
#pragma unroll
        for (int kt = 0; kt < 8; kt++) {
            int kk = kt * 16;
            qf[kt][0] = *(const uint32_t*)(p + (g    ) * KPH + kk);
            qf[kt][1] = *(const uint32_t*)(p + (g + 8) * KPH + kk);
            qf[kt][2] = *(const uint32_t*)(p + (g    ) * KPH + kk + 8);
            qf[kt][3] = *(const uint32_t*)(p + (g + 8) * KPH + kk + 8);
        }
    }
    __syncthreads();   // Q reads done before stage-0 cp.async overwrites

    auto load_kv = [&](int st, int k0) {
        __half* Ks = smh + st * ASTG;
        __half* Vs = Ks + 64 * KPH;
#pragma unroll
        for (int it = 0; it < 4; it++) {
            int f = it * 256 + tid;          // 0..1023
            int row = f >> 4, c8 = (f & 15) * 8;
            int s = k0 + row;
            int sb = (s < S_LEN) ? 16 : 0;
            size_t off = ((size_t)(s < S_LEN ? s : S_LEN - 1) * NH + head) * HD + c8;
            cp16(Ks + row * KPH + c8, RKh + off, sb);
            cp16(Vs + row * KPH + c8, Vh + off, sb);
        }
    };

    float o_acc[16][4];
#pragma unroll
    for (int nt = 0; nt < 16; nt++)
#pragma unroll
        for (int r = 0; r < 4; r++) o_acc[nt][r] = 0.f;
    float m0 = -1e30f, m1 = -1e30f, l0 = 0.f, l1 = 0.f;
    const float scale = 0.08838834764831845f;
    const int T = (S_LEN + 63) / 64;

    load_kv(0, 0);
    CP_COMMIT();
    for (int ti = 0; ti < T; ti++) {
        CP_WAIT0();
        __syncthreads();
        if (ti + 1 < T) { load_kv((ti + 1) & 1, (ti + 1) * 64); CP_COMMIT(); }
        const __half* Ks = smh + (ti & 1) * ASTG;
        const __half* Vs = Ks + 64 * KPH;
        const int k0 = ti * 64;

        // ---- scores ----
        float sf[8][4];
#pragma unroll
        for (int nt = 0; nt < 8; nt++)
#pragma unroll
            for (int r = 0; r < 4; r++) sf[nt][r] = 0.f;
#pragma unroll
        for (int kt = 0; kt < 8; kt++) {
            int kk = kt * 16 + 2 * t;
#pragma unroll
            for (int nt = 0; nt < 8; nt++) {
                const __half* p = Ks + (nt * 8 + g) * KPH + kk;
                uint32_t b0 = *(const uint32_t*)(p);
                uint32_t b1 = *(const uint32_t*)(p + 8);
                mma_f16(sf[nt], qf[kt][0], qf[kt][1], qf[kt][2], qf[kt][3], b0, b1);
            }
        }
        bool edge = (k0 + 64 > S_LEN);
#pragma unroll
        for (int nt = 0; nt < 8; nt++) {
#pragma unroll
            for (int r = 0; r < 4; r++) sf[nt][r] *= scale;
            if (edge) {
                int col = k0 + nt * 8 + 2 * t;
                if (col     >= S_LEN) { sf[nt][0] = -1e30f; sf[nt][2] = -1e30f; }
                if (col + 1 >= S_LEN) { sf[nt][1] = -1e30f; sf[nt][3] = -1e30f; }
            }
        }
        // ---- online softmax ----
        float mx0 = -1e30f, mx1 = -1e30f;
#pragma unroll
        for (int nt = 0; nt < 8; nt++) {
            mx0 = fmaxf(mx0, fmaxf(sf[nt][0], sf[nt][1]));
            mx1 = fmaxf(mx1, fmaxf(sf[nt][2], sf[nt][3]));
        }
        mx0 = fmaxf(mx0, __shfl_xor_sync(0xffffffffu, mx0, 1));
        mx0 = fmaxf(mx0, __shfl_xor_sync(0xffffffffu, mx0, 2));
        mx1 = fmaxf(mx1, __shfl_xor_sync(0xffffffffu, mx1, 1));
        mx1 = fmaxf(mx1, __shfl_xor_sync(0xffffffffu, mx1, 2));
        float mn0 = fmaxf(m0, mx0), mn1 = fmaxf(m1, mx1);
        float c0 = __expf(m0 - mn0), c1 = __expf(m1 - mn1);
        float s0 = 0.f, s1 = 0.f;
#pragma unroll
        for (int nt = 0; nt < 8; nt++) {
            sf[nt][0] = __expf(sf[nt][0] - mn0);
            sf[nt][1] = __expf(sf[nt][1] - mn0);
            sf[nt][2] = __expf(sf[nt][2] - mn1);
            sf[nt][3] = __expf(sf[nt][3] - mn1);
            s0 += sf[nt][0] + sf[nt][1];
            s1 += sf[nt][2] + sf[nt][3];
        }
        s0 += __shfl_xor_sync(0xffffffffu, s0, 1);
        s0 += __shfl_xor_sync(0xffffffffu, s0, 2);
        s1 += __shfl_xor_sync(0xffffffffu, s1, 1);
        s1 += __shfl_xor_sync(0xffffffffu, s1, 2);
        l0 = l0 * c0 + s0;  l1 = l1 * c1 + s1;
        m0 = mn0;  m1 = mn1;
#pragma unroll
        for (int nt = 0; nt < 16; nt++) {
            o_acc[nt][0] *= c0; o_acc[nt][1] *= c0;
            o_acc[nt][2] *= c1; o_acc[nt][3] *= c1;
        }
        // ---- O += P @ V ----
        const int vr = lane & 7, vq = lane >> 3;
#pragma unroll
        for (int kt = 0; kt < 4; kt++) {
            uint32_t a0 = pack_h2(sf[2*kt  ][0], sf[2*kt  ][1]);
            uint32_t a1 = pack_h2(sf[2*kt  ][2], sf[2*kt  ][3]);
            uint32_t a2 = pack_h2(sf[2*kt+1][0], sf[2*kt+1][1]);
            uint32_t a3 = pack_h2(sf[2*kt+1][2], sf[2*kt+1][3]);
#pragma unroll
            for (int nb = 0; nb < 8; nb++) {
                const __half* vp = Vs + (kt * 16 + (vq & 1) * 8 + vr) * KPH
                                      + nb * 16 + (vq >> 1) * 8;
                uint32_t v0, v1, v2, v3;
                ldmx4t(v0, v1, v2, v3, vp);
                mma_f16(o_acc[2*nb    ], a0, a1, a2, a3, v0, v1);
                mma_f16(o_acc[2*nb + 1], a0, a1, a2, a3, v2, v3);
            }
        }
        __syncthreads();
    }

    float inv0 = 1.f / l0, inv1 = 1.f / l1;
    int s0r = q0 + warp * 16 + g;
    int s1r = s0r + 8;
#pragma unroll
    for (int nt = 0; nt < 16; nt++) {
        int col = nt * 8 + 2 * t;
        if (s0r < S_LEN)
            *(float2*)(XL + ((size_t)s0r * NH + head) * HD + col) =
                make_float2(o_acc[nt][0] * inv0, o_acc[nt][1] * inv0);
        if (s1r < S_LEN)
            *(float2*)(XL + ((size_t)s1r * NH + head) * HD + col) =
                make_float2(o_acc[nt][2] * inv1, o_acc[nt][3] * inv1);
    }
}

// ---------------- launch ----------------
extern "C" void kernel_launch(void* const* d_in, const int* in_sizes, int n_in,
                              void* d_out, int out_size) {
    const float* x    = (const float*)d_in[0];
    const float* freqs= (const float*)d_in[1];
    const float* gkm  = (const float*)d_in[2];
    const float* gkv  = (const float*)d_in[3];
    const float* Wq   = (const float*)d_in[4];
    const float* bq   = (const float*)d_in[5];
    const float* Wk   = (const float*)d_in[6];
    const float* bk   = (const float*)d_in[7];
    const float* Wv   = (const float*)d_in[8];
    const float* bv   = (const float*)d_in[9];
    const float* Wo   = (const float*)d_in[10];
    const float* bo   = (const float*)d_in[11];
    const float* gq   = (const float*)d_in[12];
    const float* gk   = (const float*)d_in[13];
    const float* Wlin = (const float*)d_in[14];
    const float* blin = (const float*)d_in[15];
    float* out = (float*)d_out;

    float *Qp, *Kp, *RQp, *XLp, *Zp, *WTp;
    __half *xh, *Wqh, *Wkh, *Wvh, *Woh, *Vh, *RQh, *RKh, *XLh, *G2h;
    cudaGetSymbolAddress((void**)&Qp,  g_Q);
    cudaGetSymbolAddress((void**)&Kp,  g_K);
    cudaGetSymbolAddress((void**)&RQp, g_RQ);
    cudaGetSymbolAddress((void**)&XLp, g_XL);
    cudaGetSymbolAddress((void**)&Zp,  g_Z);
    cudaGetSymbolAddress((void**)&WTp, g_WT);
    cudaGetSymbolAddress((void**)&xh,  g_xh);
    cudaGetSymbolAddress((void**)&Wqh, g_Wqh);
    cudaGetSymbolAddress((void**)&Wkh, g_Wkh);
    cudaGetSymbolAddress((void**)&Wvh, g_Wvh);
    cudaGetSymbolAddress((void**)&Woh, g_Woh);
    cudaGetSymbolAddress((void**)&Vh,  g_Vh);
    cudaGetSymbolAddress((void**)&RQh, g_RQh);
    cudaGetSymbolAddress((void**)&RKh, g_RKh);
    cudaGetSymbolAddress((void**)&XLh, g_XLh);
    cudaGetSymbolAddress((void**)&G2h, g_G2h);

    cudaFuncSetAttribute(gemm_async_kernel<false>, cudaFuncAttributeMaxDynamicSharedMemorySize, GEMM_SMEM);
    cudaFuncSetAttribute(gemm_async_kernel<true>,  cudaFuncAttributeMaxDynamicSharedMemorySize, GEMM_SMEM);
    cudaFuncSetAttribute(attn_h_kernel, cudaFuncAttributeMaxDynamicSharedMemorySize, ATT_SMEM);
    cudaFuncSetAttribute(xg_mma_kernel, cudaFuncAttributeMaxDynamicSharedMemorySize, XG_SMEM);

    // 1. fp32 -> fp16 conversions
    {
        int n4x = S_LEN * DIM / 4, n4w = DIM * DIM / 4;
        f2h_kernel<<<(n4x + 255) / 256, 256>>>(x,  xh,  n4x);
        f2h_kernel<<<(n4w + 255) / 256, 256>>>(Wq, Wqh, n4w);
        f2h_kernel<<<(n4w + 255) / 256, 256>>>(Wk, Wkh, n4w);
        f2h_kernel<<<(n4w + 255) / 256, 256>>>(Wv, Wvh, n4w);
        f2h_kernel<<<(n4w + 255) / 256, 256>>>(Wo, Woh, n4w);
    }
    // 2. projections
    dim3 gemm_grid(DIM / 128, (S_LEN + 127) / 128);
    gemm_async_kernel<false><<<gemm_grid, 256, GEMM_SMEM>>>(xh, Wqh, bq, Qp, S_LEN, DIM, DIM);
    gemm_async_kernel<false><<<gemm_grid, 256, GEMM_SMEM>>>(xh, Wkh, bk, Kp, S_LEN, DIM, DIM);
    gemm_async_kernel<true ><<<gemm_grid, 256, GEMM_SMEM>>>(xh, Wvh, bv, Vh, S_LEN, DIM, DIM);
    // 3. rmsnorm
    rmsnorm_kernel<<<S_LEN, 256>>>(Qp, gq);
    rmsnorm_kernel<<<S_LEN, 256>>>(Kp, gk);
    // 4. z
    {
        int blocks = (S_LEN * NH * 32 + 255) / 256;
        z_kernel<<<blocks, 256>>>(Qp, gkm, Zp);
    }
    // 5. rope
    {
        int total = S_LEN * NH * 64;
        rope_kernel<<<(total + 255) / 256, 256>>>(Qp, RQp, RQh, freqs);
        rope_kernel<<<(total + 255) / 256, 256>>>(Kp, nullptr, RKh, freqs);
    }
    // 6. G2
    transpose128_kernel<<<HD, HD>>>(Wlin, WTp);
    g2_kernel<<<NH * HD, HD>>>(gkv, WTp, G2h);
    // 7. attention
    {
        dim3 grid((S_LEN + 127) / 128, NH);
        attn_h_kernel<<<grid, 256, ATT_SMEM>>>(RQh, RKh, Vh, XLp);
    }
    // 8. xg + pack to half
    {
        dim3 grid((S_LEN + 127) / 128, NH);
        xg_mma_kernel<<<grid, 256, XG_SMEM>>>(RQh, G2h, Zp, blin, XLp, XLh);
    }
    // 9. output projection
    gemm_async_kernel<false><<<gemm_grid, 256, GEMM_SMEM>>>(XLh, Woh, bo, out, S_LEN, DIM, DIM);
}

// round 6
// speedup vs baseline: 27.2571x; 1.1549x over previous
#include <cuda_runtime.h>
#include <cuda_fp16.h>
#include <math.h>
#include <stdint.h>

#define S_LEN 4680
#define DIM 1536
#define NH 12
#define HD 128

// ---------------- static scratch ----------------
__device__ float  g_Q  [S_LEN*DIM];
__device__ float  g_K  [S_LEN*DIM];
__device__ float  g_XL [S_LEN*DIM];
__device__ float  g_Z  [S_LEN*NH];
__device__ float  g_WT [HD*HD];
__device__ __half g_xh [S_LEN*DIM];
__device__ __half g_Wqh[DIM*DIM];
__device__ __half g_Wkh[DIM*DIM];
__device__ __half g_Wvh[DIM*DIM];
__device__ __half g_Woh[DIM*DIM];
__device__ __half g_Vh [S_LEN*DIM];
__device__ __half g_RQh[S_LEN*DIM];
__device__ __half g_RKh[S_LEN*DIM];
__device__ __half g_XLh[S_LEN*DIM];
__device__ __half g_G2h[NH*HD*HD];   // [n][j][d]

// ---------------- helpers ----------------
__device__ __forceinline__ uint32_t pack_h2(float lo, float hi) {
    __half2 h = __floats2half2_rn(lo, hi);
    return *reinterpret_cast<uint32_t*>(&h);
}
__device__ __forceinline__ void mma_f16(float c[4],
                                        uint32_t a0, uint32_t a1, uint32_t a2, uint32_t a3,
                                        uint32_t b0, uint32_t b1) {
    asm("mma.sync.aligned.m16n8k16.row.col.f32.f16.f16.f32 "
        "{%0,%1,%2,%3},{%4,%5,%6,%7},{%8,%9},{%0,%1,%2,%3};"
        : "+f"(c[0]), "+f"(c[1]), "+f"(c[2]), "+f"(c[3])
        : "r"(a0), "r"(a1), "r"(a2), "r"(a3), "r"(b0), "r"(b1));
}
__device__ __forceinline__ void ldmx4t(uint32_t &r0, uint32_t &r1, uint32_t &r2, uint32_t &r3,
                                       const __half* p) {
    uint32_t addr = (uint32_t)__cvta_generic_to_shared(p);
    asm volatile("ldmatrix.sync.aligned.m8n8.x4.trans.shared.b16 {%0,%1,%2,%3},[%4];"
                 : "=r"(r0), "=r"(r1), "=r"(r2), "=r"(r3) : "r"(addr));
}
__device__ __forceinline__ void cp16(__half* dst, const __half* src, int src_bytes) {
    uint32_t d = (uint32_t)__cvta_generic_to_shared(dst);
    asm volatile("cp.async.cg.shared.global [%0], [%1], 16, %2;"
                 :: "r"(d), "l"(src), "r"(src_bytes));
}
#define CP_COMMIT() asm volatile("cp.async.commit_group;")
#define CP_WAIT0()  asm volatile("cp.async.wait_group 0;")

// ---------------- batched fp32 -> fp16 convert (x + 4 weights) ----------------
__global__ void f2h_all_kernel(const float* __restrict__ x,
                               const float* __restrict__ w0, const float* __restrict__ w1,
                               const float* __restrict__ w2, const float* __restrict__ w3,
                               __half* __restrict__ xh,
                               __half* __restrict__ h0, __half* __restrict__ h1,
                               __half* __restrict__ h2, __half* __restrict__ h3) {
    const int NX = S_LEN * DIM / 4, NW = DIM * DIM / 4;
    const int total = NX + 4 * NW;
    for (int i = blockIdx.x * blockDim.x + threadIdx.x; i < total; i += gridDim.x * blockDim.x) {
        const float* src; __half* dst; int j = i;
        if (j < NX) { src = x; dst = xh; }
        else {
            j -= NX;
            int seg = j / NW; j -= seg * NW;
            src = (seg == 0) ? w0 : (seg == 1) ? w1 : (seg == 2) ? w2 : w3;
            dst = (seg == 0) ? h0 : (seg == 1) ? h1 : (seg == 2) ? h2 : h3;
        }
        float4 v = ((const float4*)src)[j];
        ((uint2*)dst)[j] = make_uint2(pack_h2(v.x, v.y), pack_h2(v.z, v.w));
    }
}

// ---------------- cp.async FP16 GEMM: C[M,N] = A @ W^T + bias ----------------
#define GKP 72
#define GEMM_SMEM (2 * 2 * 128 * GKP * 2)
template<bool HALF_OUT>
__global__ __launch_bounds__(256, 2) void gemm_async_kernel(
    const __half* __restrict__ A, const __half* __restrict__ W,
    const float* __restrict__ bias, void* __restrict__ Cout,
    int M, int N, int K) {
    extern __shared__ __half gsm[];
    const int STG = 2 * 128 * GKP;
    const int tid = threadIdx.x;
    const int warp = tid >> 5, lane = tid & 31;
    const int g = lane >> 2, t = lane & 3;
    const int wm = warp >> 2, wn = warp & 3;
    const int bm = blockIdx.y * 128, bn = blockIdx.x * 128;

    float acc[4][4][4];
#pragma unroll
    for (int i = 0; i < 4; i++)
#pragma unroll
        for (int j = 0; j < 4; j++)
#pragma unroll
            for (int r = 0; r < 4; r++) acc[i][j][r] = 0.f;

    auto load_stage = [&](int s, int k0) {
        __half* As = gsm + s * STG;
        __half* Bs = As + 128 * GKP;
#pragma unroll
        for (int it = 0; it < 4; it++) {
            int f = it * 256 + tid;
            int row = f >> 3, c8 = (f & 7) * 8;
            int gm = bm + row;
            const __half* sa = A + (size_t)(gm < M ? gm : M - 1) * K + k0 + c8;
            cp16(As + row * GKP + c8, sa, gm < M ? 16 : 0);
            const __half* sb = W + (size_t)(bn + row) * K + k0 + c8;
            cp16(Bs + row * GKP + c8, sb, 16);
        }
    };

    const int nT = K / 64;
    load_stage(0, 0);
    CP_COMMIT();
    for (int i = 0; i < nT; i++) {
        CP_WAIT0();
        __syncthreads();
        if (i + 1 < nT) { load_stage((i + 1) & 1, (i + 1) * 64); CP_COMMIT(); }
        const __half* As = gsm + (i & 1) * STG;
        const __half* Bs = As + 128 * GKP;
#pragma unroll
        for (int ks = 0; ks < 4; ks++) {
            int kk = ks * 16;
            uint32_t af[4][4], bf[4][2];
#pragma unroll
            for (int mt = 0; mt < 4; mt++) {
                const __half* p = As + (wm * 64 + mt * 16) * GKP + kk + 2 * t;
                af[mt][0] = *(const uint32_t*)(p + (g    ) * GKP);
                af[mt][1] = *(const uint32_t*)(p + (g + 8) * GKP);
                af[mt][2] = *(const uint32_t*)(p + (g    ) * GKP + 8);
                af[mt][3] = *(const uint32_t*)(p + (g + 8) * GKP + 8);
            }
#pragma unroll
            for (int nt = 0; nt < 4; nt++) {
                const __half* p = Bs + (wn * 32 + nt * 8 + g) * GKP + kk + 2 * t;
                bf[nt][0] = *(const uint32_t*)(p);
                bf[nt][1] = *(const uint32_t*)(p + 8);
            }
#pragma unroll
            for (int mt = 0; mt < 4; mt++)
#pragma unroll
                for (int nt = 0; nt < 4; nt++)
                    mma_f16(acc[mt][nt], af[mt][0], af[mt][1], af[mt][2], af[mt][3],
                            bf[nt][0], bf[nt][1]);
        }
        __syncthreads();
    }
#pragma unroll
    for (int mt = 0; mt < 4; mt++) {
#pragma unroll
        for (int nt = 0; nt < 4; nt++) {
            int col = bn + wn * 32 + nt * 8 + 2 * t;
            float2 b2 = *(const float2*)(bias + col);
            int r0 = bm + wm * 64 + mt * 16 + g;
            int r1 = r0 + 8;
            if (HALF_OUT) {
                __half* Ch = (__half*)Cout;
                if (r0 < M)
                    *(uint32_t*)(Ch + (size_t)r0 * N + col) =
                        pack_h2(acc[mt][nt][0] + b2.x, acc[mt][nt][1] + b2.y);
                if (r1 < M)
                    *(uint32_t*)(Ch + (size_t)r1 * N + col) =
                        pack_h2(acc[mt][nt][2] + b2.x, acc[mt][nt][3] + b2.y);
            } else {
                float* C = (float*)Cout;
                if (r0 < M)
                    *(float2*)(C + (size_t)r0 * N + col) =
                        make_float2(acc[mt][nt][0] + b2.x, acc[mt][nt][1] + b2.y);
                if (r1 < M)
                    *(float2*)(C + (size_t)r1 * N + col) =
                        make_float2(acc[mt][nt][2] + b2.x, acc[mt][nt][3] + b2.y);
            }
        }
    }
}

// ---------------- fused rmsnorm (+z) + rope -> fp16 ----------------
// one block (384 thr = 12 warps) per sequence row. WITH_Z: warp n computes z for head n.
template<bool WITH_Z>
__global__ __launch_bounds__(384) void qkpost_kernel(
    const float* __restrict__ X, const float* __restrict__ gw,
    const float* __restrict__ gkm, const float* __restrict__ freqs,
    __half* __restrict__ Yh, float* __restrict__ Z) {
    __shared__ float vals[DIM];
    __shared__ float red[12];
    __shared__ float s_scale;
    const int s = blockIdx.x;
    const int tid = threadIdx.x;
    const int lane = tid & 31, wid = tid >> 5;
    const float* x = X + (size_t)s * DIM;

    float ss = 0.f;
#pragma unroll
    for (int k = 0; k < 4; k++) {
        int i = tid + k * 384;
        float v = x[i];
        vals[i] = v;
        ss += v * v;
    }
#pragma unroll
    for (int o = 16; o > 0; o >>= 1) ss += __shfl_xor_sync(0xffffffffu, ss, o);
    if (lane == 0) red[wid] = ss;
    __syncthreads();
    if (wid == 0) {
        float v = (lane < 12) ? red[lane] : 0.f;
#pragma unroll
        for (int o = 8; o > 0; o >>= 1) v += __shfl_xor_sync(0xffffffffu, v, o);
        if (lane == 0) s_scale = rsqrtf(v / (float)DIM + 1e-6f);
    }
    __syncthreads();
    const float sc = s_scale;
    // normalize in smem (apply gw)
#pragma unroll
    for (int k = 0; k < 4; k++) {
        int i = tid + k * 384;
        vals[i] = vals[i] * sc * gw[i];
    }
    __syncthreads();
    // z: warp n reduces head n
    if (WITH_Z) {
        const float* vh = vals + wid * HD;
        float sum = 0.f;
#pragma unroll
        for (int k = 0; k < 4; k++) {
            int d = lane + k * 32;
            sum += fmaxf(vh[d], 0.f) * gkm[wid * HD + d];
        }
#pragma unroll
        for (int o = 16; o > 0; o >>= 1) sum += __shfl_xor_sync(0xffffffffu, sum, o);
        if (lane == 0) Z[s * NH + wid] = 1.f / (sum + 1e-6f);
    }
    // rope: position derived once
    const int w = s % 52, h = (s / 52) % 30, f = s / (52 * 30);
#pragma unroll
    for (int k = 0; k < 2; k++) {
        int p = tid + k * 384;           // pair index 0..767
        int i = p & 63;                  // pair within head
        int pos = (i < 22) ? f : (i < 43) ? h : w;
        float cr = freqs[(pos * 64 + i) * 2 + 0];
        float ci = freqs[(pos * 64 + i) * 2 + 1];
        float xr = vals[2 * p], xi = vals[2 * p + 1];
        *(uint32_t*)(Yh + (size_t)s * DIM + 2 * p) =
            pack_h2(xr * cr - xi * ci, xr * ci + xi * cr);
    }
}

// ---------------- Wlin transpose ----------------
__global__ void transpose128_kernel(const float* __restrict__ in, float* __restrict__ out) {
    int j = blockIdx.x, m = threadIdx.x;
    out[m * HD + j] = in[j * HD + m];
}

// ---------------- G2h[n][j][d] = sum_m g_kv[n,d,m] * Wlin[j,m] ----------------
__global__ void g2_kernel(const float* __restrict__ gkv, const float* __restrict__ WT,
                          __half* __restrict__ G2h) {
    int nd = blockIdx.x;
    int n = nd >> 7, d = nd & 127;
    __shared__ float kv[HD];
    kv[threadIdx.x] = gkv[(size_t)nd * HD + threadIdx.x];
    __syncthreads();
    int j = threadIdx.x;
    float sum = 0.f;
#pragma unroll 8
    for (int m = 0; m < HD; m++) sum += kv[m] * WT[m * HD + j];
    G2h[((size_t)n * HD + j) * HD + d] = __float2half(sum);
}

// ---------------- xg via tensor cores ----------------
#define KPH 136
#define XG_SMEM (2 * 128 * KPH * 2)
__global__ __launch_bounds__(256) void xg_mma_kernel(
    const __half* __restrict__ RQh, const __half* __restrict__ G2h,
    const float* __restrict__ Z, const float* __restrict__ blin,
    const float* __restrict__ XL, __half* __restrict__ XLh) {
    extern __shared__ __half xsm[];
    __half* RQs = xsm;
    __half* G2s = xsm + 128 * KPH;
    const int tid = threadIdx.x;
    const int warp = tid >> 5, lane = tid & 31;
    const int g = lane >> 2, t = lane & 3;
    const int head = blockIdx.y;
    const int q0 = blockIdx.x * 128;

#pragma unroll
    for (int it = 0; it < 8; it++) {
        int f = it * 256 + tid;
        int row = f >> 4, c8 = (f & 15) * 8;
        int s = q0 + row;
        uint4 v = make_uint4(0, 0, 0, 0);
        if (s < S_LEN) v = *(const uint4*)(RQh + ((size_t)s * NH + head) * HD + c8);
        *(uint4*)&RQs[row * KPH + c8] = v;
        uint4 gv = *(const uint4*)(G2h + ((size_t)head * HD + row) * HD + c8);
        *(uint4*)&G2s[row * KPH + c8] = gv;
    }
    __syncthreads();

    uint32_t qf[8][4];
    {
        const __half* p = RQs + (warp * 16) * KPH + 2 * t;
#pragma unroll
        for (int kt = 0; kt < 8; kt++) {
            int kk = kt * 16;
            qf[kt][0] = *(const uint32_t*)(p + (g    ) * KPH + kk);
            qf[kt][1] = *(const uint32_t*)(p + (g + 8) * KPH + kk);
            qf[kt][2] = *(const uint32_t*)(p + (g    ) * KPH + kk + 8);
            qf[kt][3] = *(const uint32_t*)(p + (g + 8) * KPH + kk + 8);
        }
    }
    float acc[16][4];
#pragma unroll
    for (int nt = 0; nt < 16; nt++)
#pragma unroll
        for (int r = 0; r < 4; r++) acc[nt][r] = 0.f;
#pragma unroll
    for (int kt = 0; kt < 8; kt++) {
        int kk = kt * 16 + 2 * t;
#pragma unroll
        for (int nt = 0; nt < 16; nt++) {
            const __half* p = G2s + (nt * 8 + g) * KPH + kk;
            uint32_t b0 = *(const uint32_t*)(p);
            uint32_t b1 = *(const uint32_t*)(p + 8);
            mma_f16(acc[nt], qf[kt][0], qf[kt][1], qf[kt][2], qf[kt][3], b0, b1);
        }
    }
    int s0r = q0 + warp * 16 + g;
    int s1r = s0r + 8;
    float z0 = (s0r < S_LEN) ? Z[s0r * NH + head] : 0.f;
    float z1 = (s1r < S_LEN) ? Z[s1r * NH + head] : 0.f;
#pragma unroll
    for (int nt = 0; nt < 16; nt++) {
        int col = nt * 8 + 2 * t;
        float2 bl = *(const float2*)(blin + col);
        if (s0r < S_LEN) {
            const float* xl = XL + ((size_t)s0r * NH + head) * HD + col;
            *(uint32_t*)(XLh + ((size_t)s0r * NH + head) * HD + col) =
                pack_h2(acc[nt][0] * z0 + bl.x + xl[0], acc[nt][1] * z0 + bl.y + xl[1]);
        }
        if (s1r < S_LEN) {
            const float* xl = XL + ((size_t)s1r * NH + head) * HD + col;
            *(uint32_t*)(XLh + ((size_t)s1r * NH + head) * HD + col) =
                pack_h2(acc[nt][2] * z1 + bl.x + xl[0], acc[nt][3] * z1 + bl.y + xl[1]);
        }
    }
}

// ---------------- FP16 flash attention, Bc=128, cp.async 2-stage ----------------
#define ASTG (2 * 128 * KPH)          // halves per stage (K+V)
#define ATT_SMEM (2 * ASTG * 2)       // 2 stages, bytes (~139KB)
__global__ __launch_bounds__(256, 1) void attn_h_kernel(
    const __half* __restrict__ RQh, const __half* __restrict__ RKh,
    const __half* __restrict__ Vh, float* __restrict__ XL) {
    extern __shared__ __half smh[];
    const int tid = threadIdx.x;
    const int warp = tid >> 5, lane = tid & 31;
    const int g = lane >> 2, t = lane & 3;
    const int head = blockIdx.y;
    const int q0 = blockIdx.x * 128;

    // stage Q in stage-0 region, read fragments
    {
        __half* Qs = smh;
#pragma unroll
        for (int it = 0; it < 8; it++) {
            int f = it * 256 + tid;
            int row = f >> 4, c8 = (f & 15) * 8;
            int s = q0 + row;
            uint4 v = make_uint4(0, 0, 0, 0);
            if (s < S_LEN) v = *(const uint4*)(RQh + ((size_t)s * NH + head) * HD + c8);
            *(uint4*)&Qs[row * KPH + c8] = v;
        }
    }
    __syncthreads();
    uint32_t qf[8][4];
    {
        const __half* p = smh + (warp * 16) * KPH + 2 * t;
#pragma unroll
        for (int kt = 0; kt < 8; kt++) {
            int kk = kt * 16;
            qf[kt][0] = *(const uint32_t*)(p + (g    ) * KPH + kk);
            qf[kt][1] = *(const uint32_t*)(p + (g + 8) * KPH + kk);
            qf[kt][2] = *(const uint32_t*)(p + (g    ) * KPH + kk + 8);
            qf[kt][3] = *(const uint32_t*)(p + (g + 8) * KPH + kk + 8);
        }
    }
    __syncthreads();

    auto load_kv = [&](int st, int k0) {
        __half* Ks = smh + st * ASTG;
        __half* Vs = Ks + 128 * KPH;
#pragma unroll
        for (int it = 0; it < 8; it++) {
            int f = it * 256 + tid;          // 0..2047
            int row = f >> 4, c8 = (f & 15) * 8;
            int s = k0 + row;
            int sb = (s < S_LEN) ? 16 : 0;
            size_t off = ((size_t)(s < S_LEN ? s : S_LEN - 1) * NH + head) * HD + c8;
            cp16(Ks + row * KPH + c8, RKh + off, sb);
            cp16(Vs + row * KPH + c8, Vh + off, sb);
        }
    };

    float o_acc[16][4];
#pragma unroll
    for (int nt = 0; nt < 16; nt++)
#pragma unroll
        for (int r = 0; r < 4; r++) o_acc[nt][r] = 0.f;
    float m0 = -1e30f, m1 = -1e30f, l0 = 0.f, l1 = 0.f;
    const float scale = 0.08838834764831845f;
    const int T = (S_LEN + 127) / 128;

    load_kv(0, 0);
    CP_COMMIT();
    for (int ti = 0; ti < T; ti++) {
        CP_WAIT0();
        __syncthreads();
        if (ti + 1 < T) { load_kv((ti + 1) & 1, (ti + 1) * 128); CP_COMMIT(); }
        const __half* Ks = smh + (ti & 1) * ASTG;
        const __half* Vs = Ks + 128 * KPH;
        const int k0 = ti * 128;

        // ---- scores S[m16][n128] ----
        float sf[16][4];
#pragma unroll
        for (int nt = 0; nt < 16; nt++)
#pragma unroll
            for (int r = 0; r < 4; r++) sf[nt][r] = 0.f;
#pragma unroll
        for (int kt = 0; kt < 8; kt++) {
            int kk = kt * 16 + 2 * t;
#pragma unroll
            for (int nt = 0; nt < 16; nt++) {
                const __half* p = Ks + (nt * 8 + g) * KPH + kk;
                uint32_t b0 = *(const uint32_t*)(p);
                uint32_t b1 = *(const uint32_t*)(p + 8);
                mma_f16(sf[nt], qf[kt][0], qf[kt][1], qf[kt][2], qf[kt][3], b0, b1);
            }
        }
        bool edge = (k0 + 128 > S_LEN);
#pragma unroll
        for (int nt = 0; nt < 16; nt++) {
#pragma unroll
            for (int r = 0; r < 4; r++) sf[nt][r] *= scale;
            if (edge) {
                int col = k0 + nt * 8 + 2 * t;
                if (col     >= S_LEN) { sf[nt][0] = -1e30f; sf[nt][2] = -1e30f; }
                if (col + 1 >= S_LEN) { sf[nt][1] = -1e30f; sf[nt][3] = -1e30f; }
            }
        }
        // ---- online softmax ----
        float mx0 = -1e30f, mx1 = -1e30f;
#pragma unroll
        for (int nt = 0; nt < 16; nt++) {
            mx0 = fmaxf(mx0, fmaxf(sf[nt][0], sf[nt][1]));
            mx1 = fmaxf(mx1, fmaxf(sf[nt][2], sf[nt][3]));
        }
        mx0 = fmaxf(mx0, __shfl_xor_sync(0xffffffffu, mx0, 1));
        mx0 = fmaxf(mx0, __shfl_xor_sync(0xffffffffu, mx0, 2));
        mx1 = fmaxf(mx1, __shfl_xor_sync(0xffffffffu, mx1, 1));
        mx1 = fmaxf(mx1, __shfl_xor_sync(0xffffffffu, mx1, 2));
        float mn0 = fmaxf(m0, mx0), mn1 = fmaxf(m1, mx1);
        float c0 = __expf(m0 - mn0), c1 = __expf(m1 - mn1);
        float s0 = 0.f, s1 = 0.f;
#pragma unroll
        for (int nt = 0; nt < 16; nt++) {
            sf[nt][0] = __expf(sf[nt][0] - mn0);
            sf[nt][1] = __expf(sf[nt][1] - mn0);
            sf[nt][2] = __expf(sf[nt][2] - mn1);
            sf[nt][3] = __expf(sf[nt][3] - mn1);
            s0 += sf[nt][0] + sf[nt][1];
            s1 += sf[nt][2] + sf[nt][3];
        }
        s0 += __shfl_xor_sync(0xffffffffu, s0, 1);
        s0 += __shfl_xor_sync(0xffffffffu, s0, 2);
        s1 += __shfl_xor_sync(0xffffffffu, s1, 1);
        s1 += __shfl_xor_sync(0xffffffffu, s1, 2);
        l0 = l0 * c0 + s0;  l1 = l1 * c1 + s1;
        m0 = mn0;  m1 = mn1;
#pragma unroll
        for (int nt = 0; nt < 16; nt++) {
            o_acc[nt][0] *= c0; o_acc[nt][1] *= c0;
            o_acc[nt][2] *= c1; o_acc[nt][3] *= c1;
        }
        // ---- O += P @ V ----
        const int vr = lane & 7, vq = lane >> 3;
#pragma unroll
        for (int kt = 0; kt < 8; kt++) {
            uint32_t a0 = pack_h2(sf[2*kt  ][0], sf[2*kt  ][1]);
            uint32_t a1 = pack_h2(sf[2*kt  ][2], sf[2*kt  ][3]);
            uint32_t a2 = pack_h2(sf[2*kt+1][0], sf[2*kt+1][1]);
            uint32_t a3 = pack_h2(sf[2*kt+1][2], sf[2*kt+1][3]);
#pragma unroll
            for (int nb = 0; nb < 8; nb++) {
                const __half* vp = Vs + (kt * 16 + (vq & 1) * 8 + vr) * KPH
                                      + nb * 16 + (vq >> 1) * 8;
                uint32_t v0, v1, v2, v3;
                ldmx4t(v0, v1, v2, v3, vp);
                mma_f16(o_acc[2*nb    ], a0, a1, a2, a3, v0, v1);
                mma_f16(o_acc[2*nb + 1], a0, a1, a2, a3, v2, v3);
            }
        }
        __syncthreads();
    }

    float inv0 = 1.f / l0, inv1 = 1.f / l1;
    int s0r = q0 + warp * 16 + g;
    int s1r = s0r + 8;
#pragma unroll
    for (int nt = 0; nt < 16; nt++) {
        int col = nt * 8 + 2 * t;
        if (s0r < S_LEN)
            *(float2*)(XL + ((size_t)s0r * NH + head) * HD + col) =
                make_float2(o_acc[nt][0] * inv0, o_acc[nt][1] * inv0);
        if (s1r < S_LEN)
            *(float2*)(XL + ((size_t)s1r * NH + head) * HD + col) =
                make_float2(o_acc[nt][2] * inv1, o_acc[nt][3] * inv1);
    }
}

// ---------------- launch ----------------
extern "C" void kernel_launch(void* const* d_in, const int* in_sizes, int n_in,
                              void* d_out, int out_size) {
    const float* x    = (const float*)d_in[0];
    const float* freqs= (const float*)d_in[1];
    const float* gkm  = (const float*)d_in[2];
    const float* gkv  = (const float*)d_in[3];
    const float* Wq   = (const float*)d_in[4];
    const float* bq   = (const float*)d_in[5];
    const float* Wk   = (const float*)d_in[6];
    const float* bk   = (const float*)d_in[7];
    const float* Wv   = (const float*)d_in[8];
    const float* bv   = (const float*)d_in[9];
    const float* Wo   = (const float*)d_in[10];
    const float* bo   = (const float*)d_in[11];
    const float* gq   = (const float*)d_in[12];
    const float* gk   = (const float*)d_in[13];
    const float* Wlin = (const float*)d_in[14];
    const float* blin = (const float*)d_in[15];
    float* out = (float*)d_out;

    float *Qp, *Kp, *XLp, *Zp, *WTp;
    __half *xh, *Wqh, *Wkh, *Wvh, *Woh, *Vh, *RQh, *RKh, *XLh, *G2h;
    cudaGetSymbolAddress((void**)&Qp,  g_Q);
    cudaGetSymbolAddress((void**)&Kp,  g_K);
    cudaGetSymbolAddress((void**)&XLp, g_XL);
    cudaGetSymbolAddress((void**)&Zp,  g_Z);
    cudaGetSymbolAddress((void**)&WTp, g_WT);
    cudaGetSymbolAddress((void**)&xh,  g_xh);
    cudaGetSymbolAddress((void**)&Wqh, g_Wqh);
    cudaGetSymbolAddress((void**)&Wkh, g_Wkh);
    cudaGetSymbolAddress((void**)&Wvh, g_Wvh);
    cudaGetSymbolAddress((void**)&Woh, g_Woh);
    cudaGetSymbolAddress((void**)&Vh,  g_Vh);
    cudaGetSymbolAddress((void**)&RQh, g_RQh);
    cudaGetSymbolAddress((void**)&RKh, g_RKh);
    cudaGetSymbolAddress((void**)&XLh, g_XLh);
    cudaGetSymbolAddress((void**)&G2h, g_G2h);

    cudaFuncSetAttribute(gemm_async_kernel<false>, cudaFuncAttributeMaxDynamicSharedMemorySize, GEMM_SMEM);
    cudaFuncSetAttribute(gemm_async_kernel<true>,  cudaFuncAttributeMaxDynamicSharedMemorySize, GEMM_SMEM);
    cudaFuncSetAttribute(attn_h_kernel, cudaFuncAttributeMaxDynamicSharedMemorySize, ATT_SMEM);
    cudaFuncSetAttribute(xg_mma_kernel, cudaFuncAttributeMaxDynamicSharedMemorySize, XG_SMEM);

    // 1. conversions (single launch)
    f2h_all_kernel<<<1024, 256>>>(x, Wq, Wk, Wv, Wo, xh, Wqh, Wkh, Wvh, Woh);
    // 2. projections
    dim3 gemm_grid(DIM / 128, (S_LEN + 127) / 128);
    gemm_async_kernel<false><<<gemm_grid, 256, GEMM_SMEM>>>(xh, Wqh, bq, Qp, S_LEN, DIM, DIM);
    gemm_async_kernel<false><<<gemm_grid, 256, GEMM_SMEM>>>(xh, Wkh, bk, Kp, S_LEN, DIM, DIM);
    gemm_async_kernel<true ><<<gemm_grid, 256, GEMM_SMEM>>>(xh, Wvh, bv, Vh, S_LEN, DIM, DIM);
    // 3. fused rmsnorm+z+rope
    qkpost_kernel<true ><<<S_LEN, 384>>>(Qp, gq, gkm, freqs, RQh, Zp);
    qkpost_kernel<false><<<S_LEN, 384>>>(Kp, gk, nullptr, freqs, RKh, nullptr);
    // 4. G2
    transpose128_kernel<<<HD, HD>>>(Wlin, WTp);
    g2_kernel<<<NH * HD, HD>>>(gkv, WTp, G2h);
    // 5. attention
    {
        dim3 grid((S_LEN + 127) / 128, NH);
        attn_h_kernel<<<grid, 256, ATT_SMEM>>>(RQh, RKh, Vh, XLp);
    }
    // 6. xg + pack
    {
        dim3 grid((S_LEN + 127) / 128, NH);
        xg_mma_kernel<<<grid, 256, XG_SMEM>>>(RQh, G2h, Zp, blin, XLp, XLh);
    }
    // 7. output projection
    gemm_async_kernel<false><<<gemm_grid, 256, GEMM_SMEM>>>(XLh, Woh, bo, out, S_LEN, DIM, DIM);
}